// round 1
// baseline (speedup 1.0000x reference)
#include <cuda_runtime.h>
#include <math.h>

// ---------------- problem constants ----------------
#define SEQ     2048
#define DMODEL  2048
#define KVDIM   512
#define NHEADS  16
#define DK      128
#define GRP     4

// ---------------- scratch (device globals; no allocs allowed) ----------------
__device__ float g_Q[SEQ * DMODEL];   // 16 MB
__device__ float g_K[SEQ * KVDIM];    //  4 MB
__device__ float g_V[SEQ * KVDIM];    //  4 MB
__device__ float g_Y[SEQ * DMODEL];   // 16 MB

// =====================================================================
// Generic SGEMM:  C[M,N] = A[M,K] @ B[N,K]^T + bias[N]
// 128x128 tile, BK=8, 256 threads, 8x8 per-thread micro-tile.
// M,N multiples of 128; K multiple of 8. All fp32.
// =====================================================================
__global__ __launch_bounds__(256) void sgemm_nt(
    const float* __restrict__ A, const float* __restrict__ B,
    const float* __restrict__ bias, float* __restrict__ C,
    int M, int N, int K)
{
    __shared__ float As[8][128];
    __shared__ float Bs[8][128];

    const int bm  = blockIdx.y * 128;
    const int bn  = blockIdx.x * 128;
    const int tid = threadIdx.x;
    const int tr  = tid >> 4;        // 0..15
    const int tc  = tid & 15;        // 0..15
    const int lr  = tid >> 1;        // 0..127
    const int lk  = (tid & 1) * 4;   // 0 or 4

    const float* Ab = A + (size_t)(bm + lr) * K + lk;
    const float* Bb = B + (size_t)(bn + lr) * K + lk;

    float acc[8][8];
#pragma unroll
    for (int i = 0; i < 8; i++)
#pragma unroll
        for (int j = 0; j < 8; j++) acc[i][j] = 0.0f;

    for (int k0 = 0; k0 < K; k0 += 8) {
        float4 av = *(const float4*)(Ab + k0);
        float4 bv = *(const float4*)(Bb + k0);
        As[lk + 0][lr] = av.x; As[lk + 1][lr] = av.y;
        As[lk + 2][lr] = av.z; As[lk + 3][lr] = av.w;
        Bs[lk + 0][lr] = bv.x; Bs[lk + 1][lr] = bv.y;
        Bs[lk + 2][lr] = bv.z; Bs[lk + 3][lr] = bv.w;
        __syncthreads();

#pragma unroll
        for (int kk = 0; kk < 8; kk++) {
            float a[8], b[8];
#pragma unroll
            for (int i = 0; i < 8; i++) a[i] = As[kk][tr * 8 + i];
#pragma unroll
            for (int j = 0; j < 8; j++) b[j] = Bs[kk][tc * 8 + j];
#pragma unroll
            for (int i = 0; i < 8; i++)
#pragma unroll
                for (int j = 0; j < 8; j++)
                    acc[i][j] += a[i] * b[j];
        }
        __syncthreads();
    }

#pragma unroll
    for (int i = 0; i < 8; i++) {
        const int row = bm + tr * 8 + i;
#pragma unroll
        for (int j = 0; j < 8; j += 4) {
            const int col = bn + tc * 8 + j;
            float4 v;
            v.x = acc[i][j + 0] + bias[col + 0];
            v.y = acc[i][j + 1] + bias[col + 1];
            v.z = acc[i][j + 2] + bias[col + 2];
            v.w = acc[i][j + 3] + bias[col + 3];
            *(float4*)&C[(size_t)row * N + col] = v;
        }
    }
}

// =====================================================================
// Flash attention (fp32, causal, GQA). One CTA = (head h, 64-query block).
// Q tile [64][128] row-major, K tile transposed [128][64], V [64][128],
// S/P staged in smem [64][65] (pad-65 => conflict-free row pass).
// 256 threads: S-GEMM 16x16 grid 4x4 tiles; PV-GEMM 16x16 grid 4rows x 8cols.
// =====================================================================
#define ATTN_SMEM_FLOATS (64*128 + 128*64 + 64*128 + 64*65 + 3*64)

__global__ __launch_bounds__(256) void attn_kernel(
    const float* __restrict__ Q, const float* __restrict__ K,
    const float* __restrict__ V, float* __restrict__ Y)
{
    extern __shared__ float sm[];
    float* Qs   = sm;                 // [64][128]
    float* Kt   = Qs + 64 * 128;      // [128][64]  (transposed)
    float* Vs   = Kt + 128 * 64;      // [64][128]
    float* Ss   = Vs + 64 * 128;      // [64][65]
    float* mrow = Ss + 64 * 65;       // [64]
    float* lrow = mrow + 64;          // [64]
    float* arow = lrow + 64;          // [64]

    const int h   = blockIdx.y;
    const int qb  = blockIdx.x;
    const int q0  = qb * 64;
    const int kvh = h >> 2;           // h / GROUP
    const int tid = threadIdx.x;
    const int tr  = tid >> 4;         // 0..15
    const int tc  = tid & 15;         // 0..15

    // ---- load Q tile (coalesced float4) ----
    for (int i = tid; i < 64 * 32; i += 256) {
        const int r  = i >> 5;
        const int d4 = (i & 31) << 2;
        *(float4*)&Qs[r * 128 + d4] =
            *(const float4*)&Q[(size_t)(q0 + r) * DMODEL + h * DK + d4];
    }
    if (tid < 64) { mrow[tid] = -1e30f; lrow[tid] = 0.0f; }

    float o[4][8];
#pragma unroll
    for (int i = 0; i < 4; i++)
#pragma unroll
        for (int j = 0; j < 8; j++) o[i][j] = 0.0f;

    const float scale = 0.08838834764831845f;   // 1/sqrt(128)

    __syncthreads();

    for (int jb = 0; jb <= qb; jb++) {
        const int k0 = jb * 64;

        // ---- load K transposed: warp spans rows => conflict-free STS ----
        for (int i = tid; i < 2048; i += 256) {
            const int r  = i & 63;
            const int d4 = (i >> 6) << 2;
            float4 kv = *(const float4*)&K[(size_t)(k0 + r) * KVDIM + kvh * DK + d4];
            Kt[(d4 + 0) * 64 + r] = kv.x;
            Kt[(d4 + 1) * 64 + r] = kv.y;
            Kt[(d4 + 2) * 64 + r] = kv.z;
            Kt[(d4 + 3) * 64 + r] = kv.w;
        }
        // ---- load V row-major (coalesced) ----
        for (int i = tid; i < 2048; i += 256) {
            const int r  = i >> 5;
            const int d4 = (i & 31) << 2;
            *(float4*)&Vs[r * 128 + d4] =
                *(const float4*)&V[(size_t)(k0 + r) * KVDIM + kvh * DK + d4];
        }
        __syncthreads();

        // ---- S = Q @ K^T : each thread 4x4 ----
        float s[4][4];
#pragma unroll
        for (int i = 0; i < 4; i++)
#pragma unroll
            for (int j = 0; j < 4; j++) s[i][j] = 0.0f;

        for (int kd = 0; kd < 128; kd++) {
            float4 bv = *(const float4*)&Kt[kd * 64 + tc * 4];
            float a[4];
#pragma unroll
            for (int i = 0; i < 4; i++) a[i] = Qs[(tr * 4 + i) * 128 + kd];
#pragma unroll
            for (int i = 0; i < 4; i++) {
                s[i][0] += a[i] * bv.x;
                s[i][1] += a[i] * bv.y;
                s[i][2] += a[i] * bv.z;
                s[i][3] += a[i] * bv.w;
            }
        }
#pragma unroll
        for (int i = 0; i < 4; i++) {
            const int r = tr * 4 + i;
#pragma unroll
            for (int j = 0; j < 4; j++) {
                const int c = tc * 4 + j;
                float val = s[i][j] * scale;
                if (k0 + c > q0 + r) val = -1e30f;   // causal mask
                Ss[r * 65 + c] = val;
            }
        }
        __syncthreads();

        // ---- online-softmax row pass (one thread per row) ----
        if (tid < 64) {
            const int r = tid;
            const float m_old = mrow[r];
            float mx = m_old;
#pragma unroll 8
            for (int c = 0; c < 64; c++) mx = fmaxf(mx, Ss[r * 65 + c]);
            const float alpha = __expf(m_old - mx);
            float sum = 0.0f;
#pragma unroll 8
            for (int c = 0; c < 64; c++) {
                const float e = __expf(Ss[r * 65 + c] - mx);
                Ss[r * 65 + c] = e;
                sum += e;
            }
            lrow[r] = lrow[r] * alpha + sum;
            mrow[r] = mx;
            arow[r] = alpha;
        }
        __syncthreads();

        // ---- O = O*alpha + P @ V : each thread 4 rows x 8 cols ----
        float al[4];
#pragma unroll
        for (int i = 0; i < 4; i++) al[i] = arow[tr * 4 + i];
#pragma unroll
        for (int i = 0; i < 4; i++)
#pragma unroll
            for (int j = 0; j < 8; j++) o[i][j] *= al[i];

        for (int kk = 0; kk < 64; kk++) {
            float p[4];
#pragma unroll
            for (int i = 0; i < 4; i++) p[i] = Ss[(tr * 4 + i) * 65 + kk];
            float4 v0 = *(const float4*)&Vs[kk * 128 + tc * 8];
            float4 v1 = *(const float4*)&Vs[kk * 128 + tc * 8 + 4];
#pragma unroll
            for (int i = 0; i < 4; i++) {
                o[i][0] += p[i] * v0.x;  o[i][1] += p[i] * v0.y;
                o[i][2] += p[i] * v0.z;  o[i][3] += p[i] * v0.w;
                o[i][4] += p[i] * v1.x;  o[i][5] += p[i] * v1.y;
                o[i][6] += p[i] * v1.z;  o[i][7] += p[i] * v1.w;
            }
        }
        __syncthreads();   // protect Kt/Vs/Ss before next tile
    }

    // ---- epilogue: divide by l, write Y[s][h*128+d] ----
#pragma unroll
    for (int i = 0; i < 4; i++) {
        const int r = tr * 4 + i;
        const float inv = 1.0f / lrow[r];
        float4 w0, w1;
        w0.x = o[i][0] * inv; w0.y = o[i][1] * inv;
        w0.z = o[i][2] * inv; w0.w = o[i][3] * inv;
        w1.x = o[i][4] * inv; w1.y = o[i][5] * inv;
        w1.z = o[i][6] * inv; w1.w = o[i][7] * inv;
        float* dst = &Y[(size_t)(q0 + r) * DMODEL + h * DK + tc * 8];
        *(float4*)(dst)     = w0;
        *(float4*)(dst + 4) = w1;
    }
}

// =====================================================================
// launch
// =====================================================================
extern "C" void kernel_launch(void* const* d_in, const int* in_sizes, int n_in,
                              void* d_out, int out_size)
{
    const float* x  = (const float*)d_in[0];
    const float* Wq = (const float*)d_in[1];
    const float* bq = (const float*)d_in[2];
    const float* Wk = (const float*)d_in[3];
    const float* bk = (const float*)d_in[4];
    const float* Wv = (const float*)d_in[5];
    const float* bv = (const float*)d_in[6];
    const float* Wo = (const float*)d_in[7];
    const float* bo = (const float*)d_in[8];
    float* out = (float*)d_out;

    float *Qb, *Kb, *Vb, *Yb;
    cudaGetSymbolAddress((void**)&Qb, g_Q);
    cudaGetSymbolAddress((void**)&Kb, g_K);
    cudaGetSymbolAddress((void**)&Vb, g_V);
    cudaGetSymbolAddress((void**)&Yb, g_Y);

    const int attn_smem = ATTN_SMEM_FLOATS * (int)sizeof(float);
    cudaFuncSetAttribute(attn_kernel,
                         cudaFuncAttributeMaxDynamicSharedMemorySize, attn_smem);

    dim3 blk(256);
    // Q projection: [2048,2048] = x @ Wq^T + bq
    sgemm_nt<<<dim3(DMODEL / 128, SEQ / 128), blk>>>(x, Wq, bq, Qb, SEQ, DMODEL, DMODEL);
    // K projection: [2048,512]
    sgemm_nt<<<dim3(KVDIM / 128, SEQ / 128), blk>>>(x, Wk, bk, Kb, SEQ, KVDIM, DMODEL);
    // V projection: [2048,512]
    sgemm_nt<<<dim3(KVDIM / 128, SEQ / 128), blk>>>(x, Wv, bv, Vb, SEQ, KVDIM, DMODEL);
    // attention: grid (query blocks, heads)
    attn_kernel<<<dim3(SEQ / 64, NHEADS), blk, attn_smem>>>(Qb, Kb, Vb, Yb);
    // output projection: out = Y @ Wo^T + bo
    sgemm_nt<<<dim3(DMODEL / 128, SEQ / 128), blk>>>(Yb, Wo, bo, out, SEQ, DMODEL, DMODEL);
}

// round 3
// speedup vs baseline: 1.8823x; 1.8823x over previous
#include <cuda_runtime.h>
#include <cstdint>
#include <math.h>

// ---------------- problem constants ----------------
#define SEQ     2048
#define DMODEL  2048
#define KVDIM   512
#define NHEADS  16
#define DK      128

// ---------------- scratch (device globals; no allocs allowed) ----------------
__device__ float g_Q[SEQ * DMODEL];
__device__ float g_K[SEQ * KVDIM];
__device__ float g_V[SEQ * KVDIM];
__device__ float g_Y[SEQ * DMODEL];
// tf32-rounded copies of GEMM inputs
__device__ float g_xt [SEQ * DMODEL];
__device__ float g_Wqt[DMODEL * DMODEL];
__device__ float g_Wkt[KVDIM * DMODEL];
__device__ float g_Wvt[KVDIM * DMODEL];
__device__ float g_Wot[DMODEL * DMODEL];

// =====================================================================
// tf32 rounding pass: out[i] = round_to_nearest_tf32(in[i])
// =====================================================================
__global__ void cvt_tf32_kernel(const float4* __restrict__ in,
                                float4* __restrict__ out, int n4) {
    int i = blockIdx.x * blockDim.x + threadIdx.x;
    if (i >= n4) return;
    float4 v = in[i];
    uint32_t a, b, c, d;
    asm("cvt.rna.tf32.f32 %0, %1;" : "=r"(a) : "f"(v.x));
    asm("cvt.rna.tf32.f32 %0, %1;" : "=r"(b) : "f"(v.y));
    asm("cvt.rna.tf32.f32 %0, %1;" : "=r"(c) : "f"(v.z));
    asm("cvt.rna.tf32.f32 %0, %1;" : "=r"(d) : "f"(v.w));
    float4 o;
    o.x = __uint_as_float(a); o.y = __uint_as_float(b);
    o.z = __uint_as_float(c); o.w = __uint_as_float(d);
    out[i] = o;
}

// =====================================================================
// tf32 mma.sync GEMM:  C[M,N] = A[M,K] @ B[N,K]^T + bias[N]
// CTA tile 128x128, 256 thr (8 warps, 2x4), warp tile 64x32,
// mma.m16n8k8.tf32, BK=32, double-buffered cp.async.
// SMEM rows padded to 36 floats (conflict-free LDS, 16B aligned).
// =====================================================================
#define BK      32
#define PAD     36
#define TILE_F  (128 * PAD)            // floats per tile
#define STAGE_F (2 * TILE_F)           // A + B
#define GEMM_SMEM_BYTES (2 * STAGE_F * 4)   // 2 stages = 73728 B

__device__ __forceinline__ void cpasync16(uint32_t saddr, const void* gaddr) {
    asm volatile("cp.async.cg.shared.global [%0], [%1], 16;" :: "r"(saddr), "l"(gaddr) : "memory");
}

__device__ __forceinline__ void mma_tf32(float c[4], const uint32_t a[4], const uint32_t b[2]) {
    asm volatile(
        "mma.sync.aligned.m16n8k8.row.col.f32.tf32.tf32.f32 "
        "{%0,%1,%2,%3}, {%4,%5,%6,%7}, {%8,%9}, {%0,%1,%2,%3};"
        : "+f"(c[0]), "+f"(c[1]), "+f"(c[2]), "+f"(c[3])
        : "r"(a[0]), "r"(a[1]), "r"(a[2]), "r"(a[3]), "r"(b[0]), "r"(b[1]));
}

__global__ __launch_bounds__(256) void gemm_tf32(
    const float* __restrict__ A, const float* __restrict__ B,
    const float* __restrict__ bias, float* __restrict__ C,
    int M, int N, int K)
{
    extern __shared__ float sm[];

    const int tid  = threadIdx.x;
    const int wid  = tid >> 5;
    const int lane = tid & 31;
    const int gid  = lane >> 2;       // 0..7
    const int tig  = lane & 3;        // 0..3
    const int wm   = wid >> 2;        // 0..1 : 64-row slab
    const int wn   = wid & 3;         // 0..3 : 32-col slab
    const int bm   = blockIdx.y * 128;
    const int bn   = blockIdx.x * 128;
    const int nchunk = K >> 5;

    const uint32_t smem_u32 = (uint32_t)__cvta_generic_to_shared(sm);

    // cp.async loader for one chunk into stage s
    auto load_chunk = [&](int s, int j) {
        const uint32_t sA = smem_u32 + (s * STAGE_F) * 4;
        const uint32_t sB = sA + TILE_F * 4;
        const float* Ag = A + (size_t)bm * K + j * BK;
        const float* Bg = B + (size_t)bn * K + j * BK;
#pragma unroll
        for (int it = 0; it < 4; it++) {
            const int idx = tid + it * 256;   // 0..1023
            const int r = idx >> 3;           // 0..127
            const int c = idx & 7;            // 16B chunk
            const uint32_t soff = (r * PAD + c * 4) * 4;
            cpasync16(sA + soff, Ag + (size_t)r * K + c * 4);
            cpasync16(sB + soff, Bg + (size_t)r * K + c * 4);
        }
        asm volatile("cp.async.commit_group;" ::: "memory");
    };

    float acc[4][4][4];
#pragma unroll
    for (int mf = 0; mf < 4; mf++)
#pragma unroll
        for (int nf = 0; nf < 4; nf++)
#pragma unroll
            for (int q = 0; q < 4; q++) acc[mf][nf][q] = 0.0f;

    load_chunk(0, 0);

    for (int i = 0; i < nchunk; i++) {
        if (i + 1 < nchunk) {
            load_chunk((i + 1) & 1, i + 1);
            asm volatile("cp.async.wait_group 1;" ::: "memory");
        } else {
            asm volatile("cp.async.wait_group 0;" ::: "memory");
        }
        __syncthreads();

        const float* sA = sm + (i & 1) * STAGE_F;
        const float* sB = sA + TILE_F;
        const float* aW = sA + (wm * 64) * PAD;   // warp's 64-row slab
        const float* bW = sB + (wn * 32) * PAD;   // warp's 32-row (=col) slab

#pragma unroll
        for (int kk = 0; kk < 4; kk++) {
            const int k0 = kk * 8;
            uint32_t af[4][4];
#pragma unroll
            for (int mf = 0; mf < 4; mf++) {
                const float* ap = aW + (mf * 16 + gid) * PAD + k0 + tig;
                af[mf][0] = __float_as_uint(ap[0]);
                af[mf][1] = __float_as_uint(ap[8 * PAD]);
                af[mf][2] = __float_as_uint(ap[4]);
                af[mf][3] = __float_as_uint(ap[8 * PAD + 4]);
            }
            uint32_t bf[4][2];
#pragma unroll
            for (int nf = 0; nf < 4; nf++) {
                const float* bp = bW + (nf * 8 + gid) * PAD + k0 + tig;
                bf[nf][0] = __float_as_uint(bp[0]);
                bf[nf][1] = __float_as_uint(bp[4]);
            }
#pragma unroll
            for (int mf = 0; mf < 4; mf++)
#pragma unroll
                for (int nf = 0; nf < 4; nf++)
                    mma_tf32(acc[mf][nf], af[mf], bf[nf]);
        }
        __syncthreads();
    }

    // ---- epilogue: write C with bias (float2 per fragment row) ----
#pragma unroll
    for (int mf = 0; mf < 4; mf++) {
        const int row = bm + wm * 64 + mf * 16 + gid;
#pragma unroll
        for (int nf = 0; nf < 4; nf++) {
            const int col = bn + wn * 32 + nf * 8 + 2 * tig;
            const float b0 = bias[col], b1 = bias[col + 1];
            float2 v0; v0.x = acc[mf][nf][0] + b0; v0.y = acc[mf][nf][1] + b1;
            float2 v1; v1.x = acc[mf][nf][2] + b0; v1.y = acc[mf][nf][3] + b1;
            *(float2*)&C[(size_t)row * N + col]       = v0;
            *(float2*)&C[(size_t)(row + 8) * N + col] = v1;
        }
    }
}

// =====================================================================
// Flash attention (fp32, causal, GQA) — unchanged
// =====================================================================
#define ATTN_SMEM_FLOATS (64*128 + 128*64 + 64*128 + 64*65 + 3*64)

__global__ __launch_bounds__(256) void attn_kernel(
    const float* __restrict__ Q, const float* __restrict__ K,
    const float* __restrict__ V, float* __restrict__ Y)
{
    extern __shared__ float sm[];
    float* Qs   = sm;
    float* Kt   = Qs + 64 * 128;
    float* Vs   = Kt + 128 * 64;
    float* Ss   = Vs + 64 * 128;
    float* mrow = Ss + 64 * 65;
    float* lrow = mrow + 64;
    float* arow = lrow + 64;

    const int h   = blockIdx.y;
    const int qb  = blockIdx.x;
    const int q0  = qb * 64;
    const int kvh = h >> 2;
    const int tid = threadIdx.x;
    const int tr  = tid >> 4;
    const int tc  = tid & 15;

    for (int i = tid; i < 64 * 32; i += 256) {
        const int r  = i >> 5;
        const int d4 = (i & 31) << 2;
        *(float4*)&Qs[r * 128 + d4] =
            *(const float4*)&Q[(size_t)(q0 + r) * DMODEL + h * DK + d4];
    }
    if (tid < 64) { mrow[tid] = -1e30f; lrow[tid] = 0.0f; }

    float o[4][8];
#pragma unroll
    for (int i = 0; i < 4; i++)
#pragma unroll
        for (int j = 0; j < 8; j++) o[i][j] = 0.0f;

    const float scale = 0.08838834764831845f;
    __syncthreads();

    for (int jb = 0; jb <= qb; jb++) {
        const int k0 = jb * 64;
        for (int i = tid; i < 2048; i += 256) {
            const int r  = i & 63;
            const int d4 = (i >> 6) << 2;
            float4 kv = *(const float4*)&K[(size_t)(k0 + r) * KVDIM + kvh * DK + d4];
            Kt[(d4 + 0) * 64 + r] = kv.x;
            Kt[(d4 + 1) * 64 + r] = kv.y;
            Kt[(d4 + 2) * 64 + r] = kv.z;
            Kt[(d4 + 3) * 64 + r] = kv.w;
        }
        for (int i = tid; i < 2048; i += 256) {
            const int r  = i >> 5;
            const int d4 = (i & 31) << 2;
            *(float4*)&Vs[r * 128 + d4] =
                *(const float4*)&V[(size_t)(k0 + r) * KVDIM + kvh * DK + d4];
        }
        __syncthreads();

        float s[4][4];
#pragma unroll
        for (int i = 0; i < 4; i++)
#pragma unroll
            for (int j = 0; j < 4; j++) s[i][j] = 0.0f;

        for (int kd = 0; kd < 128; kd++) {
            float4 bv = *(const float4*)&Kt[kd * 64 + tc * 4];
            float a[4];
#pragma unroll
            for (int i = 0; i < 4; i++) a[i] = Qs[(tr * 4 + i) * 128 + kd];
#pragma unroll
            for (int i = 0; i < 4; i++) {
                s[i][0] += a[i] * bv.x;
                s[i][1] += a[i] * bv.y;
                s[i][2] += a[i] * bv.z;
                s[i][3] += a[i] * bv.w;
            }
        }
#pragma unroll
        for (int i = 0; i < 4; i++) {
            const int r = tr * 4 + i;
#pragma unroll
            for (int j = 0; j < 4; j++) {
                const int c = tc * 4 + j;
                float val = s[i][j] * scale;
                if (k0 + c > q0 + r) val = -1e30f;
                Ss[r * 65 + c] = val;
            }
        }
        __syncthreads();

        if (tid < 64) {
            const int r = tid;
            const float m_old = mrow[r];
            float mx = m_old;
#pragma unroll 8
            for (int c = 0; c < 64; c++) mx = fmaxf(mx, Ss[r * 65 + c]);
            const float alpha = __expf(m_old - mx);
            float sum = 0.0f;
#pragma unroll 8
            for (int c = 0; c < 64; c++) {
                const float e = __expf(Ss[r * 65 + c] - mx);
                Ss[r * 65 + c] = e;
                sum += e;
            }
            lrow[r] = lrow[r] * alpha + sum;
            mrow[r] = mx;
            arow[r] = alpha;
        }
        __syncthreads();

        float al[4];
#pragma unroll
        for (int i = 0; i < 4; i++) al[i] = arow[tr * 4 + i];
#pragma unroll
        for (int i = 0; i < 4; i++)
#pragma unroll
            for (int j = 0; j < 8; j++) o[i][j] *= al[i];

        for (int kk = 0; kk < 64; kk++) {
            float p[4];
#pragma unroll
            for (int i = 0; i < 4; i++) p[i] = Ss[(tr * 4 + i) * 65 + kk];
            float4 v0 = *(const float4*)&Vs[kk * 128 + tc * 8];
            float4 v1 = *(const float4*)&Vs[kk * 128 + tc * 8 + 4];
#pragma unroll
            for (int i = 0; i < 4; i++) {
                o[i][0] += p[i] * v0.x;  o[i][1] += p[i] * v0.y;
                o[i][2] += p[i] * v0.z;  o[i][3] += p[i] * v0.w;
                o[i][4] += p[i] * v1.x;  o[i][5] += p[i] * v1.y;
                o[i][6] += p[i] * v1.z;  o[i][7] += p[i] * v1.w;
            }
        }
        __syncthreads();
    }

#pragma unroll
    for (int i = 0; i < 4; i++) {
        const int r = tr * 4 + i;
        const float inv = 1.0f / lrow[r];
        float4 w0, w1;
        w0.x = o[i][0] * inv; w0.y = o[i][1] * inv;
        w0.z = o[i][2] * inv; w0.w = o[i][3] * inv;
        w1.x = o[i][4] * inv; w1.y = o[i][5] * inv;
        w1.z = o[i][6] * inv; w1.w = o[i][7] * inv;
        float* dst = &Y[(size_t)(q0 + r) * DMODEL + h * DK + tc * 8];
        *(float4*)(dst)     = w0;
        *(float4*)(dst + 4) = w1;
    }
}

// =====================================================================
// launch
// =====================================================================
extern "C" void kernel_launch(void* const* d_in, const int* in_sizes, int n_in,
                              void* d_out, int out_size)
{
    const float* x  = (const float*)d_in[0];
    const float* Wq = (const float*)d_in[1];
    const float* bq = (const float*)d_in[2];
    const float* Wk = (const float*)d_in[3];
    const float* bk = (const float*)d_in[4];
    const float* Wv = (const float*)d_in[5];
    const float* bv = (const float*)d_in[6];
    const float* Wo = (const float*)d_in[7];
    const float* bo = (const float*)d_in[8];
    float* out = (float*)d_out;

    float *Qb, *Kb, *Vb, *Yb, *xt, *Wqt, *Wkt, *Wvt, *Wot;
    cudaGetSymbolAddress((void**)&Qb, g_Q);
    cudaGetSymbolAddress((void**)&Kb, g_K);
    cudaGetSymbolAddress((void**)&Vb, g_V);
    cudaGetSymbolAddress((void**)&Yb, g_Y);
    cudaGetSymbolAddress((void**)&xt, g_xt);
    cudaGetSymbolAddress((void**)&Wqt, g_Wqt);
    cudaGetSymbolAddress((void**)&Wkt, g_Wkt);
    cudaGetSymbolAddress((void**)&Wvt, g_Wvt);
    cudaGetSymbolAddress((void**)&Wot, g_Wot);

    cudaFuncSetAttribute(gemm_tf32,
                         cudaFuncAttributeMaxDynamicSharedMemorySize, GEMM_SMEM_BYTES);
    const int attn_smem = ATTN_SMEM_FLOATS * (int)sizeof(float);
    cudaFuncSetAttribute(attn_kernel,
                         cudaFuncAttributeMaxDynamicSharedMemorySize, attn_smem);

    dim3 blk(256);
    const int cvt_blk = 256;
    const int n4_big = SEQ * DMODEL / 4;
    const int n4_kv  = KVDIM * DMODEL / 4;

    cvt_tf32_kernel<<<(n4_big + cvt_blk - 1) / cvt_blk, cvt_blk>>>((const float4*)x,  (float4*)xt,  n4_big);
    cvt_tf32_kernel<<<(n4_big + cvt_blk - 1) / cvt_blk, cvt_blk>>>((const float4*)Wq, (float4*)Wqt, n4_big);
    cvt_tf32_kernel<<<(n4_kv  + cvt_blk - 1) / cvt_blk, cvt_blk>>>((const float4*)Wk, (float4*)Wkt, n4_kv);
    cvt_tf32_kernel<<<(n4_kv  + cvt_blk - 1) / cvt_blk, cvt_blk>>>((const float4*)Wv, (float4*)Wvt, n4_kv);
    cvt_tf32_kernel<<<(n4_big + cvt_blk - 1) / cvt_blk, cvt_blk>>>((const float4*)Wo, (float4*)Wot, n4_big);

    gemm_tf32<<<dim3(DMODEL / 128, SEQ / 128), blk, GEMM_SMEM_BYTES>>>(xt, Wqt, bq, Qb, SEQ, DMODEL, DMODEL);
    gemm_tf32<<<dim3(KVDIM  / 128, SEQ / 128), blk, GEMM_SMEM_BYTES>>>(xt, Wkt, bk, Kb, SEQ, KVDIM, DMODEL);
    gemm_tf32<<<dim3(KVDIM  / 128, SEQ / 128), blk, GEMM_SMEM_BYTES>>>(xt, Wvt, bv, Vb, SEQ, KVDIM, DMODEL);

    attn_kernel<<<dim3(SEQ / 64, NHEADS), blk, attn_smem>>>(Qb, Kb, Vb, Yb);

    cvt_tf32_kernel<<<(n4_big + cvt_blk - 1) / cvt_blk, cvt_blk>>>((const float4*)Yb, (float4*)Yb, n4_big);
    gemm_tf32<<<dim3(DMODEL / 128, SEQ / 128), blk, GEMM_SMEM_BYTES>>>(Yb, Wot, bo, out, SEQ, DMODEL, DMODEL);
}

// round 4
// speedup vs baseline: 3.4758x; 1.8465x over previous
#include <cuda_runtime.h>
#include <cstdint>
#include <math.h>

// ---------------- problem constants ----------------
#define SEQ     2048
#define DMODEL  2048
#define KVDIM   512
#define NHEADS  16
#define DK      128

// ---------------- scratch (device globals; no allocs allowed) ----------------
__device__ float g_Q[SEQ * DMODEL];
__device__ float g_K[SEQ * KVDIM];
__device__ float g_V[SEQ * KVDIM];
__device__ float g_Y[SEQ * DMODEL];
// tf32-rounded copies of GEMM inputs
__device__ float g_xt [SEQ * DMODEL];
__device__ float g_Wqt[DMODEL * DMODEL];
__device__ float g_Wkt[KVDIM * DMODEL];
__device__ float g_Wvt[KVDIM * DMODEL];
__device__ float g_Wot[DMODEL * DMODEL];

// =====================================================================
// helpers
// =====================================================================
__device__ __forceinline__ float rnaf(float x) {
    uint32_t u;
    asm("cvt.rna.tf32.f32 %0, %1;" : "=r"(u) : "f"(x));
    return __uint_as_float(u);
}

__device__ __forceinline__ void cpasync16(uint32_t saddr, const void* gaddr) {
    asm volatile("cp.async.cg.shared.global [%0], [%1], 16;" :: "r"(saddr), "l"(gaddr) : "memory");
}

__device__ __forceinline__ void mma_tf32(float c[4], const uint32_t a[4], const uint32_t b[2]) {
    asm volatile(
        "mma.sync.aligned.m16n8k8.row.col.f32.tf32.tf32.f32 "
        "{%0,%1,%2,%3}, {%4,%5,%6,%7}, {%8,%9}, {%0,%1,%2,%3};"
        : "+f"(c[0]), "+f"(c[1]), "+f"(c[2]), "+f"(c[3])
        : "r"(a[0]), "r"(a[1]), "r"(a[2]), "r"(a[3]), "r"(b[0]), "r"(b[1]));
}

// =====================================================================
// tf32 rounding pass
// =====================================================================
__global__ void cvt_tf32_kernel(const float4* __restrict__ in,
                                float4* __restrict__ out, int n4) {
    int i = blockIdx.x * blockDim.x + threadIdx.x;
    if (i >= n4) return;
    float4 v = in[i];
    float4 o;
    o.x = rnaf(v.x); o.y = rnaf(v.y); o.z = rnaf(v.z); o.w = rnaf(v.w);
    out[i] = o;
}

// =====================================================================
// tf32 mma.sync GEMM (unchanged from R3)
// =====================================================================
#define BK      32
#define PAD     36
#define TILE_F  (128 * PAD)
#define STAGE_F (2 * TILE_F)
#define GEMM_SMEM_BYTES (2 * STAGE_F * 4)

__global__ __launch_bounds__(256) void gemm_tf32(
    const float* __restrict__ A, const float* __restrict__ B,
    const float* __restrict__ bias, float* __restrict__ C,
    int M, int N, int K)
{
    extern __shared__ float sm[];

    const int tid  = threadIdx.x;
    const int wid  = tid >> 5;
    const int lane = tid & 31;
    const int gid  = lane >> 2;
    const int tig  = lane & 3;
    const int wm   = wid >> 2;
    const int wn   = wid & 3;
    const int bm   = blockIdx.y * 128;
    const int bn   = blockIdx.x * 128;
    const int nchunk = K >> 5;

    const uint32_t smem_u32 = (uint32_t)__cvta_generic_to_shared(sm);

    auto load_chunk = [&](int s, int j) {
        const uint32_t sA = smem_u32 + (s * STAGE_F) * 4;
        const uint32_t sB = sA + TILE_F * 4;
        const float* Ag = A + (size_t)bm * K + j * BK;
        const float* Bg = B + (size_t)bn * K + j * BK;
#pragma unroll
        for (int it = 0; it < 4; it++) {
            const int idx = tid + it * 256;
            const int r = idx >> 3;
            const int c = idx & 7;
            const uint32_t soff = (r * PAD + c * 4) * 4;
            cpasync16(sA + soff, Ag + (size_t)r * K + c * 4);
            cpasync16(sB + soff, Bg + (size_t)r * K + c * 4);
        }
        asm volatile("cp.async.commit_group;" ::: "memory");
    };

    float acc[4][4][4];
#pragma unroll
    for (int mf = 0; mf < 4; mf++)
#pragma unroll
        for (int nf = 0; nf < 4; nf++)
#pragma unroll
            for (int q = 0; q < 4; q++) acc[mf][nf][q] = 0.0f;

    load_chunk(0, 0);

    for (int i = 0; i < nchunk; i++) {
        if (i + 1 < nchunk) {
            load_chunk((i + 1) & 1, i + 1);
            asm volatile("cp.async.wait_group 1;" ::: "memory");
        } else {
            asm volatile("cp.async.wait_group 0;" ::: "memory");
        }
        __syncthreads();

        const float* sA = sm + (i & 1) * STAGE_F;
        const float* sB = sA + TILE_F;
        const float* aW = sA + (wm * 64) * PAD;
        const float* bW = sB + (wn * 32) * PAD;

#pragma unroll
        for (int kk = 0; kk < 4; kk++) {
            const int k0 = kk * 8;
            uint32_t af[4][4];
#pragma unroll
            for (int mf = 0; mf < 4; mf++) {
                const float* ap = aW + (mf * 16 + gid) * PAD + k0 + tig;
                af[mf][0] = __float_as_uint(ap[0]);
                af[mf][1] = __float_as_uint(ap[8 * PAD]);
                af[mf][2] = __float_as_uint(ap[4]);
                af[mf][3] = __float_as_uint(ap[8 * PAD + 4]);
            }
            uint32_t bf[4][2];
#pragma unroll
            for (int nf = 0; nf < 4; nf++) {
                const float* bp = bW + (nf * 8 + gid) * PAD + k0 + tig;
                bf[nf][0] = __float_as_uint(bp[0]);
                bf[nf][1] = __float_as_uint(bp[4]);
            }
#pragma unroll
            for (int mf = 0; mf < 4; mf++)
#pragma unroll
                for (int nf = 0; nf < 4; nf++)
                    mma_tf32(acc[mf][nf], af[mf], bf[nf]);
        }
        __syncthreads();
    }

#pragma unroll
    for (int mf = 0; mf < 4; mf++) {
        const int row = bm + wm * 64 + mf * 16 + gid;
#pragma unroll
        for (int nf = 0; nf < 4; nf++) {
            const int col = bn + wn * 32 + nf * 8 + 2 * tig;
            const float b0 = bias[col], b1 = bias[col + 1];
            float2 v0; v0.x = acc[mf][nf][0] + b0; v0.y = acc[mf][nf][1] + b1;
            float2 v1; v1.x = acc[mf][nf][2] + b0; v1.y = acc[mf][nf][3] + b1;
            *(float2*)&C[(size_t)row * N + col]       = v0;
            *(float2*)&C[(size_t)(row + 8) * N + col] = v1;
        }
    }
}

// =====================================================================
// Flash attention v2: tf32 mma.sync, causal, GQA.
// CTA = (head, 128-query block), 256 thr, 8 warps x 16 rows.
// Key tile 64. Q/K/V rna-rounded in smem; fp32 softmax in registers;
// P through per-warp smem tile; O in registers.
// Epilogue writes Y already rna-rounded for the O-projection GEMM.
// =====================================================================
#define QT    128
#define KT    64
#define DPAD  132
#define PPAD  66
#define ATTN_SMEM_BYTES ((QT*DPAD + 2*KT*DPAD + QT*PPAD) * 4)

__global__ __launch_bounds__(256) void attn_tc_kernel(
    const float* __restrict__ Q, const float* __restrict__ K,
    const float* __restrict__ V, float* __restrict__ Y)
{
    extern __shared__ float sm[];
    float* Qs = sm;                     // [128][132]
    float* Ks = Qs + QT * DPAD;         // [64][132]
    float* Vs = Ks + KT * DPAD;         // [64][132]
    float* Ps = Vs + KT * DPAD;         // [128][66]

    const int h   = blockIdx.y;
    const int qb  = (gridDim.x - 1) - blockIdx.x;   // heavy blocks first
    const int q0  = qb * QT;
    const int kvh = h >> 2;
    const int tid = threadIdx.x;
    const int wid = tid >> 5;
    const int lane = tid & 31;
    const int gid = lane >> 2;
    const int tig = lane & 3;
    const int w16 = wid * 16;

    // ---- load Q tile (rna to tf32) ----
    for (int i = tid; i < QT * 32; i += 256) {
        const int r  = i >> 5;
        const int c4 = (i & 31) << 2;
        float4 v = *(const float4*)&Q[(size_t)(q0 + r) * DMODEL + h * DK + c4];
        float4 o;
        o.x = rnaf(v.x); o.y = rnaf(v.y); o.z = rnaf(v.z); o.w = rnaf(v.w);
        *(float4*)&Qs[r * DPAD + c4] = o;
    }

    float o_acc[16][4];
#pragma unroll
    for (int nf = 0; nf < 16; nf++)
#pragma unroll
        for (int q = 0; q < 4; q++) o_acc[nf][q] = 0.0f;

    float m0 = -1e30f, m1 = -1e30f, l0 = 0.0f, l1 = 0.0f;
    const float scale = 0.08838834764831845f;   // 1/sqrt(128)
    const int rg0 = q0 + w16 + gid;
    const int rg1 = rg0 + 8;

    __syncthreads();

    const int njb = 2 * qb + 2;
    for (int jb = 0; jb < njb; jb++) {
        const int k0 = jb * KT;

        // ---- load K,V tiles (rna) ----
        for (int i = tid; i < KT * 32; i += 256) {
            const int r  = i >> 5;
            const int c4 = (i & 31) << 2;
            const size_t goff = (size_t)(k0 + r) * KVDIM + kvh * DK + c4;
            float4 kv = *(const float4*)&K[goff];
            float4 vv = *(const float4*)&V[goff];
            float4 ko, vo;
            ko.x = rnaf(kv.x); ko.y = rnaf(kv.y); ko.z = rnaf(kv.z); ko.w = rnaf(kv.w);
            vo.x = rnaf(vv.x); vo.y = rnaf(vv.y); vo.z = rnaf(vv.z); vo.w = rnaf(vv.w);
            *(float4*)&Ks[r * DPAD + c4] = ko;
            *(float4*)&Vs[r * DPAD + c4] = vo;
        }
        __syncthreads();

        // ---- S = Q @ K^T  (warp tile 16x64, fp32 acc) ----
        float s[8][4];
#pragma unroll
        for (int nf = 0; nf < 8; nf++)
#pragma unroll
            for (int q = 0; q < 4; q++) s[nf][q] = 0.0f;

#pragma unroll
        for (int kk = 0; kk < 16; kk++) {
            const int kd = kk * 8;
            uint32_t a[4];
            const float* ap = &Qs[(w16 + gid) * DPAD + kd + tig];
            a[0] = __float_as_uint(ap[0]);
            a[1] = __float_as_uint(ap[8 * DPAD]);
            a[2] = __float_as_uint(ap[4]);
            a[3] = __float_as_uint(ap[8 * DPAD + 4]);
#pragma unroll
            for (int nf = 0; nf < 8; nf++) {
                uint32_t b[2];
                const float* bp = &Ks[(nf * 8 + gid) * DPAD + kd + tig];
                b[0] = __float_as_uint(bp[0]);
                b[1] = __float_as_uint(bp[4]);
                mma_tf32(s[nf], a, b);
            }
        }

        // ---- scale + causal mask + online softmax ----
        const bool need_mask = (jb >= 2 * qb);
        float mx0 = -1e30f, mx1 = -1e30f;
#pragma unroll
        for (int nf = 0; nf < 8; nf++) {
#pragma unroll
            for (int e = 0; e < 2; e++) {
                const int jg = k0 + nf * 8 + 2 * tig + e;
                float v0 = s[nf][e]     * scale;
                float v1 = s[nf][2 + e] * scale;
                if (need_mask) {
                    if (jg > rg0) v0 = -1e30f;
                    if (jg > rg1) v1 = -1e30f;
                }
                s[nf][e]     = v0;
                s[nf][2 + e] = v1;
                mx0 = fmaxf(mx0, v0);
                mx1 = fmaxf(mx1, v1);
            }
        }
        mx0 = fmaxf(mx0, __shfl_xor_sync(0xffffffffu, mx0, 1));
        mx0 = fmaxf(mx0, __shfl_xor_sync(0xffffffffu, mx0, 2));
        mx1 = fmaxf(mx1, __shfl_xor_sync(0xffffffffu, mx1, 1));
        mx1 = fmaxf(mx1, __shfl_xor_sync(0xffffffffu, mx1, 2));

        const float mn0 = fmaxf(m0, mx0);
        const float mn1 = fmaxf(m1, mx1);
        const float al0 = __expf(m0 - mn0);
        const float al1 = __expf(m1 - mn1);
        m0 = mn0; m1 = mn1;

        float sum0 = 0.0f, sum1 = 0.0f;
#pragma unroll
        for (int nf = 0; nf < 8; nf++) {
            float p00 = __expf(s[nf][0] - mn0);
            float p01 = __expf(s[nf][1] - mn0);
            float p10 = __expf(s[nf][2] - mn1);
            float p11 = __expf(s[nf][3] - mn1);
            sum0 += p00 + p01;
            sum1 += p10 + p11;
            float2 w0; w0.x = rnaf(p00); w0.y = rnaf(p01);
            float2 w1; w1.x = rnaf(p10); w1.y = rnaf(p11);
            const int pc = nf * 8 + 2 * tig;
            *(float2*)&Ps[(w16 + gid)     * PPAD + pc] = w0;
            *(float2*)&Ps[(w16 + gid + 8) * PPAD + pc] = w1;
        }
        sum0 += __shfl_xor_sync(0xffffffffu, sum0, 1);
        sum0 += __shfl_xor_sync(0xffffffffu, sum0, 2);
        sum1 += __shfl_xor_sync(0xffffffffu, sum1, 1);
        sum1 += __shfl_xor_sync(0xffffffffu, sum1, 2);
        l0 = l0 * al0 + sum0;
        l1 = l1 * al1 + sum1;

        // rescale O
#pragma unroll
        for (int nf = 0; nf < 16; nf++) {
            o_acc[nf][0] *= al0; o_acc[nf][1] *= al0;
            o_acc[nf][2] *= al1; o_acc[nf][3] *= al1;
        }
        __syncwarp();

        // ---- O += P @ V  (warp tile 16x128 over 64 keys) ----
#pragma unroll
        for (int kk = 0; kk < 8; kk++) {
            const int kb = kk * 8;
            uint32_t a[4];
            const float* pp = &Ps[(w16 + gid) * PPAD + kb + tig];
            a[0] = __float_as_uint(pp[0]);
            a[1] = __float_as_uint(pp[8 * PPAD]);
            a[2] = __float_as_uint(pp[4]);
            a[3] = __float_as_uint(pp[8 * PPAD + 4]);
#pragma unroll
            for (int nf = 0; nf < 16; nf++) {
                uint32_t b[2];
                const float* vp = &Vs[(kb + tig) * DPAD + nf * 8 + gid];
                b[0] = __float_as_uint(vp[0]);
                b[1] = __float_as_uint(vp[4 * DPAD]);
                mma_tf32(o_acc[nf], a, b);
            }
        }
        __syncthreads();   // K/V/(P) reuse next tile
    }

    // ---- epilogue: divide by l, rna-round, write Y ----
    const float inv0 = 1.0f / l0;
    const float inv1 = 1.0f / l1;
#pragma unroll
    for (int nf = 0; nf < 16; nf++) {
        const int col = h * DK + nf * 8 + 2 * tig;
        float2 v0, v1;
        v0.x = rnaf(o_acc[nf][0] * inv0); v0.y = rnaf(o_acc[nf][1] * inv0);
        v1.x = rnaf(o_acc[nf][2] * inv1); v1.y = rnaf(o_acc[nf][3] * inv1);
        *(float2*)&Y[(size_t)rg0 * DMODEL + col] = v0;
        *(float2*)&Y[(size_t)rg1 * DMODEL + col] = v1;
    }
}

// =====================================================================
// launch
// =====================================================================
extern "C" void kernel_launch(void* const* d_in, const int* in_sizes, int n_in,
                              void* d_out, int out_size)
{
    const float* x  = (const float*)d_in[0];
    const float* Wq = (const float*)d_in[1];
    const float* bq = (const float*)d_in[2];
    const float* Wk = (const float*)d_in[3];
    const float* bk = (const float*)d_in[4];
    const float* Wv = (const float*)d_in[5];
    const float* bv = (const float*)d_in[6];
    const float* Wo = (const float*)d_in[7];
    const float* bo = (const float*)d_in[8];
    float* out = (float*)d_out;

    float *Qb, *Kb, *Vb, *Yb, *xt, *Wqt, *Wkt, *Wvt, *Wot;
    cudaGetSymbolAddress((void**)&Qb, g_Q);
    cudaGetSymbolAddress((void**)&Kb, g_K);
    cudaGetSymbolAddress((void**)&Vb, g_V);
    cudaGetSymbolAddress((void**)&Yb, g_Y);
    cudaGetSymbolAddress((void**)&xt, g_xt);
    cudaGetSymbolAddress((void**)&Wqt, g_Wqt);
    cudaGetSymbolAddress((void**)&Wkt, g_Wkt);
    cudaGetSymbolAddress((void**)&Wvt, g_Wvt);
    cudaGetSymbolAddress((void**)&Wot, g_Wot);

    cudaFuncSetAttribute(gemm_tf32,
                         cudaFuncAttributeMaxDynamicSharedMemorySize, GEMM_SMEM_BYTES);
    cudaFuncSetAttribute(attn_tc_kernel,
                         cudaFuncAttributeMaxDynamicSharedMemorySize, ATTN_SMEM_BYTES);

    dim3 blk(256);
    const int cvt_blk = 256;
    const int n4_big = SEQ * DMODEL / 4;
    const int n4_kv  = KVDIM * DMODEL / 4;

    cvt_tf32_kernel<<<(n4_big + cvt_blk - 1) / cvt_blk, cvt_blk>>>((const float4*)x,  (float4*)xt,  n4_big);
    cvt_tf32_kernel<<<(n4_big + cvt_blk - 1) / cvt_blk, cvt_blk>>>((const float4*)Wq, (float4*)Wqt, n4_big);
    cvt_tf32_kernel<<<(n4_kv  + cvt_blk - 1) / cvt_blk, cvt_blk>>>((const float4*)Wk, (float4*)Wkt, n4_kv);
    cvt_tf32_kernel<<<(n4_kv  + cvt_blk - 1) / cvt_blk, cvt_blk>>>((const float4*)Wv, (float4*)Wvt, n4_kv);
    cvt_tf32_kernel<<<(n4_big + cvt_blk - 1) / cvt_blk, cvt_blk>>>((const float4*)Wo, (float4*)Wot, n4_big);

    gemm_tf32<<<dim3(DMODEL / 128, SEQ / 128), blk, GEMM_SMEM_BYTES>>>(xt, Wqt, bq, Qb, SEQ, DMODEL, DMODEL);
    gemm_tf32<<<dim3(KVDIM  / 128, SEQ / 128), blk, GEMM_SMEM_BYTES>>>(xt, Wkt, bk, Kb, SEQ, KVDIM, DMODEL);
    gemm_tf32<<<dim3(KVDIM  / 128, SEQ / 128), blk, GEMM_SMEM_BYTES>>>(xt, Wvt, bv, Vb, SEQ, KVDIM, DMODEL);

    attn_tc_kernel<<<dim3(SEQ / QT, NHEADS), blk, ATTN_SMEM_BYTES>>>(Qb, Kb, Vb, Yb);

    gemm_tf32<<<dim3(DMODEL / 128, SEQ / 128), blk, GEMM_SMEM_BYTES>>>(Yb, Wot, bo, out, SEQ, DMODEL, DMODEL);
}

// round 5
// speedup vs baseline: 3.8203x; 1.0991x over previous
#include <cuda_runtime.h>
#include <cstdint>
#include <math.h>

// ---------------- problem constants ----------------
#define SEQ     2048
#define DMODEL  2048
#define KVDIM   512
#define NHEADS  16
#define DK      128
#define NQKV    (DMODEL + 2 * KVDIM)    // 3072 fused projection width

// ---------------- scratch (device globals; no allocs allowed) ----------------
__device__ float g_QKV [SEQ * NQKV];          // fused Q|K|V projections
__device__ float g_Y   [SEQ * DMODEL];
__device__ float g_xt  [SEQ * DMODEL];        // tf32-rounded x
__device__ float g_Wqkv[NQKV * DMODEL];       // tf32-rounded fused weights
__device__ float g_bqkv[NQKV];                // fused bias
__device__ float g_Wot [DMODEL * DMODEL];     // tf32-rounded Wo

// =====================================================================
// helpers
// =====================================================================
__device__ __forceinline__ float rnaf(float x) {
    uint32_t u;
    asm("cvt.rna.tf32.f32 %0, %1;" : "=r"(u) : "f"(x));
    return __uint_as_float(u);
}

__device__ __forceinline__ void cpasync16(uint32_t saddr, const void* gaddr) {
    asm volatile("cp.async.cg.shared.global [%0], [%1], 16;" :: "r"(saddr), "l"(gaddr) : "memory");
}

__device__ __forceinline__ void mma_tf32(float c[4], const uint32_t a[4], const uint32_t b[2]) {
    asm volatile(
        "mma.sync.aligned.m16n8k8.row.col.f32.tf32.tf32.f32 "
        "{%0,%1,%2,%3}, {%4,%5,%6,%7}, {%8,%9}, {%0,%1,%2,%3};"
        : "+f"(c[0]), "+f"(c[1]), "+f"(c[2]), "+f"(c[3])
        : "r"(a[0]), "r"(a[1]), "r"(a[2]), "r"(a[3]), "r"(b[0]), "r"(b[1]));
}

// =====================================================================
// tf32 rounding pass
// =====================================================================
__global__ void cvt_tf32_kernel(const float4* __restrict__ in,
                                float4* __restrict__ out, int n4) {
    int i = blockIdx.x * blockDim.x + threadIdx.x;
    if (i >= n4) return;
    float4 v = in[i];
    float4 o;
    o.x = rnaf(v.x); o.y = rnaf(v.y); o.z = rnaf(v.z); o.w = rnaf(v.w);
    out[i] = o;
}

// fused bias assembly: [bq | bk | bv]
__global__ void fuse_bias_kernel(const float* __restrict__ bq,
                                 const float* __restrict__ bk,
                                 const float* __restrict__ bv,
                                 float* __restrict__ b) {
    int i = blockIdx.x * blockDim.x + threadIdx.x;
    if (i >= NQKV) return;
    float v;
    if (i < DMODEL)              v = bq[i];
    else if (i < DMODEL + KVDIM) v = bk[i - DMODEL];
    else                         v = bv[i - DMODEL - KVDIM];
    b[i] = v;
}

// =====================================================================
// tf32 mma.sync GEMM:  C[M,N] = A[M,K] @ B[N,K]^T + bias[N]
// CTA tile 128x128, 256 thr (8 warps, 2x4), warp tile 64x32,
// m16n8k8.tf32, BK=32, 3-stage cp.async pipeline (lookahead 2),
// one __syncthreads per chunk. 2 CTAs/SM.
// =====================================================================
#define BK      32
#define PAD     36
#define TILE_F  (128 * PAD)
#define STAGE_F (2 * TILE_F)
#define NSTAGE  3
#define GEMM_SMEM_BYTES (NSTAGE * STAGE_F * 4)   // 110,592 B

__global__ __launch_bounds__(256, 2) void gemm_tf32(
    const float* __restrict__ A, const float* __restrict__ B,
    const float* __restrict__ bias, float* __restrict__ C,
    int M, int N, int K)
{
    extern __shared__ float sm[];

    const int tid  = threadIdx.x;
    const int wid  = tid >> 5;
    const int lane = tid & 31;
    const int gid  = lane >> 2;
    const int tig  = lane & 3;
    const int wm   = wid >> 2;
    const int wn   = wid & 3;
    const int bm   = blockIdx.y * 128;
    const int bn   = blockIdx.x * 128;
    const int nchunk = K >> 5;

    const uint32_t smem_u32 = (uint32_t)__cvta_generic_to_shared(sm);

    auto load_chunk = [&](int s, int j) {
        const uint32_t sA = smem_u32 + (s * STAGE_F) * 4;
        const uint32_t sB = sA + TILE_F * 4;
        const float* Ag = A + (size_t)bm * K + j * BK;
        const float* Bg = B + (size_t)bn * K + j * BK;
#pragma unroll
        for (int it = 0; it < 4; it++) {
            const int idx = tid + it * 256;
            const int r = idx >> 3;
            const int c = idx & 7;
            const uint32_t soff = (r * PAD + c * 4) * 4;
            cpasync16(sA + soff, Ag + (size_t)r * K + c * 4);
            cpasync16(sB + soff, Bg + (size_t)r * K + c * 4);
        }
        asm volatile("cp.async.commit_group;" ::: "memory");
    };

    float acc[4][4][4];
#pragma unroll
    for (int mf = 0; mf < 4; mf++)
#pragma unroll
        for (int nf = 0; nf < 4; nf++)
#pragma unroll
            for (int q = 0; q < 4; q++) acc[mf][nf][q] = 0.0f;

    // prologue: 2 chunks in flight
    load_chunk(0, 0);
    if (nchunk > 1) load_chunk(1, 1);

    int cs = 0;          // compute stage
    int ls = 2;          // next stage to fill
    for (int i = 0; i < nchunk; i++) {
        // chunk i must be complete
        if (i + 1 < nchunk) {
            asm volatile("cp.async.wait_group 1;" ::: "memory");
        } else {
            asm volatile("cp.async.wait_group 0;" ::: "memory");
        }
        __syncthreads();   // all warps past compute of chunk i-1; stage ls free

        const int j = i + 2;
        if (j < nchunk) {
            load_chunk(ls, j);
            ls = (ls == NSTAGE - 1) ? 0 : ls + 1;
        }

        const float* sA = sm + cs * STAGE_F;
        const float* sB = sA + TILE_F;
        const float* aW = sA + (wm * 64) * PAD;
        const float* bW = sB + (wn * 32) * PAD;
        cs = (cs == NSTAGE - 1) ? 0 : cs + 1;

#pragma unroll
        for (int kk = 0; kk < 4; kk++) {
            const int k0 = kk * 8;
            uint32_t af[4][4];
#pragma unroll
            for (int mf = 0; mf < 4; mf++) {
                const float* ap = aW + (mf * 16 + gid) * PAD + k0 + tig;
                af[mf][0] = __float_as_uint(ap[0]);
                af[mf][1] = __float_as_uint(ap[8 * PAD]);
                af[mf][2] = __float_as_uint(ap[4]);
                af[mf][3] = __float_as_uint(ap[8 * PAD + 4]);
            }
            uint32_t bf[4][2];
#pragma unroll
            for (int nf = 0; nf < 4; nf++) {
                const float* bp = bW + (nf * 8 + gid) * PAD + k0 + tig;
                bf[nf][0] = __float_as_uint(bp[0]);
                bf[nf][1] = __float_as_uint(bp[4]);
            }
#pragma unroll
            for (int mf = 0; mf < 4; mf++)
#pragma unroll
                for (int nf = 0; nf < 4; nf++)
                    mma_tf32(acc[mf][nf], af[mf], bf[nf]);
        }
    }

#pragma unroll
    for (int mf = 0; mf < 4; mf++) {
        const int row = bm + wm * 64 + mf * 16 + gid;
#pragma unroll
        for (int nf = 0; nf < 4; nf++) {
            const int col = bn + wn * 32 + nf * 8 + 2 * tig;
            const float b0 = bias[col], b1 = bias[col + 1];
            float2 v0; v0.x = acc[mf][nf][0] + b0; v0.y = acc[mf][nf][1] + b1;
            float2 v1; v1.x = acc[mf][nf][2] + b0; v1.y = acc[mf][nf][3] + b1;
            *(float2*)&C[(size_t)row * N + col]       = v0;
            *(float2*)&C[(size_t)(row + 8) * N + col] = v1;
        }
    }
}

// =====================================================================
// Flash attention v2: tf32 mma.sync, causal, GQA.
// Reads Q/K/V from the fused projection buffer (row stride NQKV).
// =====================================================================
#define QT    128
#define KT    64
#define DPAD  132
#define PPAD  66
#define ATTN_SMEM_BYTES ((QT*DPAD + 2*KT*DPAD + QT*PPAD) * 4)

__global__ __launch_bounds__(256) void attn_tc_kernel(
    const float* __restrict__ QKV, float* __restrict__ Y)
{
    extern __shared__ float sm[];
    float* Qs = sm;                     // [128][132]
    float* Ks = Qs + QT * DPAD;         // [64][132]
    float* Vs = Ks + KT * DPAD;         // [64][132]
    float* Ps = Vs + KT * DPAD;         // [128][66]

    const int h   = blockIdx.y;
    const int qb  = (gridDim.x - 1) - blockIdx.x;   // heavy blocks first
    const int q0  = qb * QT;
    const int kvh = h >> 2;
    const int tid = threadIdx.x;
    const int wid = tid >> 5;
    const int lane = tid & 31;
    const int gid = lane >> 2;
    const int tig = lane & 3;
    const int w16 = wid * 16;

    const float* Qg = QKV + h * DK;                       // stride NQKV
    const float* Kg = QKV + DMODEL + kvh * DK;            // stride NQKV
    const float* Vg = QKV + DMODEL + KVDIM + kvh * DK;    // stride NQKV

    // ---- load Q tile (rna to tf32) ----
    for (int i = tid; i < QT * 32; i += 256) {
        const int r  = i >> 5;
        const int c4 = (i & 31) << 2;
        float4 v = *(const float4*)&Qg[(size_t)(q0 + r) * NQKV + c4];
        float4 o;
        o.x = rnaf(v.x); o.y = rnaf(v.y); o.z = rnaf(v.z); o.w = rnaf(v.w);
        *(float4*)&Qs[r * DPAD + c4] = o;
    }

    float o_acc[16][4];
#pragma unroll
    for (int nf = 0; nf < 16; nf++)
#pragma unroll
        for (int q = 0; q < 4; q++) o_acc[nf][q] = 0.0f;

    float m0 = -1e30f, m1 = -1e30f, l0 = 0.0f, l1 = 0.0f;
    const float scale = 0.08838834764831845f;   // 1/sqrt(128)
    const int rg0 = q0 + w16 + gid;
    const int rg1 = rg0 + 8;

    __syncthreads();

    const int njb = 2 * qb + 2;
    for (int jb = 0; jb < njb; jb++) {
        const int k0 = jb * KT;

        // ---- load K,V tiles (rna) ----
        for (int i = tid; i < KT * 32; i += 256) {
            const int r  = i >> 5;
            const int c4 = (i & 31) << 2;
            const size_t goff = (size_t)(k0 + r) * NQKV + c4;
            float4 kv = *(const float4*)&Kg[goff];
            float4 vv = *(const float4*)&Vg[goff];
            float4 ko, vo;
            ko.x = rnaf(kv.x); ko.y = rnaf(kv.y); ko.z = rnaf(kv.z); ko.w = rnaf(kv.w);
            vo.x = rnaf(vv.x); vo.y = rnaf(vv.y); vo.z = rnaf(vv.z); vo.w = rnaf(vv.w);
            *(float4*)&Ks[r * DPAD + c4] = ko;
            *(float4*)&Vs[r * DPAD + c4] = vo;
        }
        __syncthreads();

        // ---- S = Q @ K^T ----
        float s[8][4];
#pragma unroll
        for (int nf = 0; nf < 8; nf++)
#pragma unroll
            for (int q = 0; q < 4; q++) s[nf][q] = 0.0f;

#pragma unroll
        for (int kk = 0; kk < 16; kk++) {
            const int kd = kk * 8;
            uint32_t a[4];
            const float* ap = &Qs[(w16 + gid) * DPAD + kd + tig];
            a[0] = __float_as_uint(ap[0]);
            a[1] = __float_as_uint(ap[8 * DPAD]);
            a[2] = __float_as_uint(ap[4]);
            a[3] = __float_as_uint(ap[8 * DPAD + 4]);
#pragma unroll
            for (int nf = 0; nf < 8; nf++) {
                uint32_t b[2];
                const float* bp = &Ks[(nf * 8 + gid) * DPAD + kd + tig];
                b[0] = __float_as_uint(bp[0]);
                b[1] = __float_as_uint(bp[4]);
                mma_tf32(s[nf], a, b);
            }
        }

        // ---- scale + causal mask + online softmax ----
        const bool need_mask = (jb >= 2 * qb);
        float mx0 = -1e30f, mx1 = -1e30f;
#pragma unroll
        for (int nf = 0; nf < 8; nf++) {
#pragma unroll
            for (int e = 0; e < 2; e++) {
                const int jg = k0 + nf * 8 + 2 * tig + e;
                float v0 = s[nf][e]     * scale;
                float v1 = s[nf][2 + e] * scale;
                if (need_mask) {
                    if (jg > rg0) v0 = -1e30f;
                    if (jg > rg1) v1 = -1e30f;
                }
                s[nf][e]     = v0;
                s[nf][2 + e] = v1;
                mx0 = fmaxf(mx0, v0);
                mx1 = fmaxf(mx1, v1);
            }
        }
        mx0 = fmaxf(mx0, __shfl_xor_sync(0xffffffffu, mx0, 1));
        mx0 = fmaxf(mx0, __shfl_xor_sync(0xffffffffu, mx0, 2));
        mx1 = fmaxf(mx1, __shfl_xor_sync(0xffffffffu, mx1, 1));
        mx1 = fmaxf(mx1, __shfl_xor_sync(0xffffffffu, mx1, 2));

        const float mn0 = fmaxf(m0, mx0);
        const float mn1 = fmaxf(m1, mx1);
        const float al0 = __expf(m0 - mn0);
        const float al1 = __expf(m1 - mn1);
        m0 = mn0; m1 = mn1;

        float sum0 = 0.0f, sum1 = 0.0f;
#pragma unroll
        for (int nf = 0; nf < 8; nf++) {
            float p00 = __expf(s[nf][0] - mn0);
            float p01 = __expf(s[nf][1] - mn0);
            float p10 = __expf(s[nf][2] - mn1);
            float p11 = __expf(s[nf][3] - mn1);
            sum0 += p00 + p01;
            sum1 += p10 + p11;
            float2 w0; w0.x = rnaf(p00); w0.y = rnaf(p01);
            float2 w1; w1.x = rnaf(p10); w1.y = rnaf(p11);
            const int pc = nf * 8 + 2 * tig;
            *(float2*)&Ps[(w16 + gid)     * PPAD + pc] = w0;
            *(float2*)&Ps[(w16 + gid + 8) * PPAD + pc] = w1;
        }
        sum0 += __shfl_xor_sync(0xffffffffu, sum0, 1);
        sum0 += __shfl_xor_sync(0xffffffffu, sum0, 2);
        sum1 += __shfl_xor_sync(0xffffffffu, sum1, 1);
        sum1 += __shfl_xor_sync(0xffffffffu, sum1, 2);
        l0 = l0 * al0 + sum0;
        l1 = l1 * al1 + sum1;

#pragma unroll
        for (int nf = 0; nf < 16; nf++) {
            o_acc[nf][0] *= al0; o_acc[nf][1] *= al0;
            o_acc[nf][2] *= al1; o_acc[nf][3] *= al1;
        }
        __syncwarp();

        // ---- O += P @ V ----
#pragma unroll
        for (int kk = 0; kk < 8; kk++) {
            const int kb = kk * 8;
            uint32_t a[4];
            const float* pp = &Ps[(w16 + gid) * PPAD + kb + tig];
            a[0] = __float_as_uint(pp[0]);
            a[1] = __float_as_uint(pp[8 * PPAD]);
            a[2] = __float_as_uint(pp[4]);
            a[3] = __float_as_uint(pp[8 * PPAD + 4]);
#pragma unroll
            for (int nf = 0; nf < 16; nf++) {
                uint32_t b[2];
                const float* vp = &Vs[(kb + tig) * DPAD + nf * 8 + gid];
                b[0] = __float_as_uint(vp[0]);
                b[1] = __float_as_uint(vp[4 * DPAD]);
                mma_tf32(o_acc[nf], a, b);
            }
        }
        __syncthreads();
    }

    // ---- epilogue: divide by l, rna-round, write Y ----
    const float inv0 = 1.0f / l0;
    const float inv1 = 1.0f / l1;
#pragma unroll
    for (int nf = 0; nf < 16; nf++) {
        const int col = h * DK + nf * 8 + 2 * tig;
        float2 v0, v1;
        v0.x = rnaf(o_acc[nf][0] * inv0); v0.y = rnaf(o_acc[nf][1] * inv0);
        v1.x = rnaf(o_acc[nf][2] * inv1); v1.y = rnaf(o_acc[nf][3] * inv1);
        *(float2*)&Y[(size_t)rg0 * DMODEL + col] = v0;
        *(float2*)&Y[(size_t)rg1 * DMODEL + col] = v1;
    }
}

// =====================================================================
// launch
// =====================================================================
extern "C" void kernel_launch(void* const* d_in, const int* in_sizes, int n_in,
                              void* d_out, int out_size)
{
    const float* x  = (const float*)d_in[0];
    const float* Wq = (const float*)d_in[1];
    const float* bq = (const float*)d_in[2];
    const float* Wk = (const float*)d_in[3];
    const float* bk = (const float*)d_in[4];
    const float* Wv = (const float*)d_in[5];
    const float* bv = (const float*)d_in[6];
    const float* Wo = (const float*)d_in[7];
    const float* bo = (const float*)d_in[8];
    float* out = (float*)d_out;

    float *QKVb, *Yb, *xt, *Wqkv, *bqkv, *Wot;
    cudaGetSymbolAddress((void**)&QKVb, g_QKV);
    cudaGetSymbolAddress((void**)&Yb,   g_Y);
    cudaGetSymbolAddress((void**)&xt,   g_xt);
    cudaGetSymbolAddress((void**)&Wqkv, g_Wqkv);
    cudaGetSymbolAddress((void**)&bqkv, g_bqkv);
    cudaGetSymbolAddress((void**)&Wot,  g_Wot);

    cudaFuncSetAttribute(gemm_tf32,
                         cudaFuncAttributeMaxDynamicSharedMemorySize, GEMM_SMEM_BYTES);
    cudaFuncSetAttribute(attn_tc_kernel,
                         cudaFuncAttributeMaxDynamicSharedMemorySize, ATTN_SMEM_BYTES);

    dim3 blk(256);
    const int cvt_blk = 256;
    const int n4_big = SEQ * DMODEL / 4;            // 2048*2048/4
    const int n4_kv  = KVDIM * DMODEL / 4;

    // tf32 round x and weights (weights into fused buffer)
    cvt_tf32_kernel<<<(n4_big + cvt_blk - 1) / cvt_blk, cvt_blk>>>((const float4*)x,  (float4*)xt, n4_big);
    cvt_tf32_kernel<<<(n4_big + cvt_blk - 1) / cvt_blk, cvt_blk>>>((const float4*)Wq, (float4*)(Wqkv), n4_big);
    cvt_tf32_kernel<<<(n4_kv  + cvt_blk - 1) / cvt_blk, cvt_blk>>>((const float4*)Wk, (float4*)(Wqkv + (size_t)DMODEL * DMODEL), n4_kv);
    cvt_tf32_kernel<<<(n4_kv  + cvt_blk - 1) / cvt_blk, cvt_blk>>>((const float4*)Wv, (float4*)(Wqkv + (size_t)(DMODEL + KVDIM) * DMODEL), n4_kv);
    cvt_tf32_kernel<<<(n4_big + cvt_blk - 1) / cvt_blk, cvt_blk>>>((const float4*)Wo, (float4*)Wot, n4_big);
    fuse_bias_kernel<<<(NQKV + 255) / 256, 256>>>(bq, bk, bv, bqkv);

    // fused QKV projection: [2048,3072]
    gemm_tf32<<<dim3(NQKV / 128, SEQ / 128), blk, GEMM_SMEM_BYTES>>>(xt, Wqkv, bqkv, QKVb, SEQ, NQKV, DMODEL);

    // attention
    attn_tc_kernel<<<dim3(SEQ / QT, NHEADS), blk, ATTN_SMEM_BYTES>>>(QKVb, Yb);

    // output projection
    gemm_tf32<<<dim3(DMODEL / 128, SEQ / 128), blk, GEMM_SMEM_BYTES>>>(Yb, Wot, bo, out, SEQ, DMODEL, DMODEL);
}

// round 6
// speedup vs baseline: 4.3821x; 1.1471x over previous
#include <cuda_runtime.h>
#include <cstdint>
#include <math.h>

// ---------------- problem constants ----------------
#define SEQ     2048
#define DMODEL  2048
#define KVDIM   512
#define NHEADS  16
#define DK      128
#define NQKV    (DMODEL + 2 * KVDIM)    // 3072 fused projection width

// ---------------- scratch (device globals; no allocs allowed) ----------------
__device__ float g_QKV [SEQ * NQKV];
__device__ float g_Y   [SEQ * DMODEL];
__device__ float g_xt  [SEQ * DMODEL];
__device__ float g_Wqkv[NQKV * DMODEL];
__device__ float g_bqkv[NQKV];
__device__ float g_Wot [DMODEL * DMODEL];

// =====================================================================
// helpers
// =====================================================================
__device__ __forceinline__ float rnaf(float x) {
    uint32_t u;
    asm("cvt.rna.tf32.f32 %0, %1;" : "=r"(u) : "f"(x));
    return __uint_as_float(u);
}

__device__ __forceinline__ void cpasync16(uint32_t saddr, const void* gaddr) {
    asm volatile("cp.async.cg.shared.global [%0], [%1], 16;" :: "r"(saddr), "l"(gaddr) : "memory");
}

__device__ __forceinline__ void mma_tf32(float c[4], const uint32_t a[4], const uint32_t b[2]) {
    asm volatile(
        "mma.sync.aligned.m16n8k8.row.col.f32.tf32.tf32.f32 "
        "{%0,%1,%2,%3}, {%4,%5,%6,%7}, {%8,%9}, {%0,%1,%2,%3};"
        : "+f"(c[0]), "+f"(c[1]), "+f"(c[2]), "+f"(c[3])
        : "r"(a[0]), "r"(a[1]), "r"(a[2]), "r"(a[3]), "r"(b[0]), "r"(b[1]));
}

// ldmatrix x4: each 8x8-b16 tile = 8 rows x 16B = 8x4 fp32;
// thread t receives fp32 (t/4, t%4) of tile i in reg i.
__device__ __forceinline__ void ldsm_x4(uint32_t r[4], uint32_t addr) {
    asm volatile("ldmatrix.sync.aligned.m8n8.x4.shared.b16 {%0,%1,%2,%3}, [%4];"
                 : "=r"(r[0]), "=r"(r[1]), "=r"(r[2]), "=r"(r[3]) : "r"(addr));
}

// =====================================================================
// tf32 rounding pass
// =====================================================================
__global__ void cvt_tf32_kernel(const float4* __restrict__ in,
                                float4* __restrict__ out, int n4) {
    int i = blockIdx.x * blockDim.x + threadIdx.x;
    if (i >= n4) return;
    float4 v = in[i];
    float4 o;
    o.x = rnaf(v.x); o.y = rnaf(v.y); o.z = rnaf(v.z); o.w = rnaf(v.w);
    out[i] = o;
}

__global__ void fuse_bias_kernel(const float* __restrict__ bq,
                                 const float* __restrict__ bk,
                                 const float* __restrict__ bv,
                                 float* __restrict__ b) {
    int i = blockIdx.x * blockDim.x + threadIdx.x;
    if (i >= NQKV) return;
    float v;
    if (i < DMODEL)              v = bq[i];
    else if (i < DMODEL + KVDIM) v = bk[i - DMODEL];
    else                         v = bv[i - DMODEL - KVDIM];
    b[i] = v;
}

// =====================================================================
// tf32 mma.sync GEMM with ldmatrix fragment loads.
// CTA tile 128x128, 8 warps (2x4), warp tile 64x32, BK=32,
// 3-stage cp.async pipeline, 2 CTAs/SM.
// =====================================================================
#define BK      32
#define PAD     36
#define TILE_F  (128 * PAD)
#define STAGE_F (2 * TILE_F)
#define NSTAGE  3
#define GEMM_SMEM_BYTES (NSTAGE * STAGE_F * 4)

__global__ __launch_bounds__(256, 2) void gemm_tf32(
    const float* __restrict__ A, const float* __restrict__ B,
    const float* __restrict__ bias, float* __restrict__ C,
    int M, int N, int K)
{
    extern __shared__ float sm[];

    const int tid  = threadIdx.x;
    const int wid  = tid >> 5;
    const int lane = tid & 31;
    const int gid  = lane >> 2;
    const int tig  = lane & 3;
    const int wm   = wid >> 2;
    const int wn   = wid & 3;
    const int bm   = blockIdx.y * 128;
    const int bn   = blockIdx.x * 128;
    const int nchunk = K >> 5;

    // ldmatrix per-thread address components
    const int arow = lane & 15;                       // A tile row
    const int acsh = (lane >> 4) * 4;                 // A col shift (k+4 half)
    const int brow = ((lane >> 4) << 3) + (lane & 7); // B row across 2 n-tiles
    const int bcsh = ((lane >> 3) & 1) * 4;           // B col shift

    const uint32_t smem_u32 = (uint32_t)__cvta_generic_to_shared(sm);

    auto load_chunk = [&](int s, int j) {
        const uint32_t sA = smem_u32 + (s * STAGE_F) * 4;
        const uint32_t sB = sA + TILE_F * 4;
        const float* Ag = A + (size_t)bm * K + j * BK;
        const float* Bg = B + (size_t)bn * K + j * BK;
#pragma unroll
        for (int it = 0; it < 4; it++) {
            const int idx = tid + it * 256;
            const int r = idx >> 3;
            const int c = idx & 7;
            const uint32_t soff = (r * PAD + c * 4) * 4;
            cpasync16(sA + soff, Ag + (size_t)r * K + c * 4);
            cpasync16(sB + soff, Bg + (size_t)r * K + c * 4);
        }
        asm volatile("cp.async.commit_group;" ::: "memory");
    };

    float acc[4][4][4];
#pragma unroll
    for (int mf = 0; mf < 4; mf++)
#pragma unroll
        for (int nf = 0; nf < 4; nf++)
#pragma unroll
            for (int q = 0; q < 4; q++) acc[mf][nf][q] = 0.0f;

    load_chunk(0, 0);
    if (nchunk > 1) load_chunk(1, 1);

    int cs = 0;
    int ls = 2;
    for (int i = 0; i < nchunk; i++) {
        if (i + 1 < nchunk) {
            asm volatile("cp.async.wait_group 1;" ::: "memory");
        } else {
            asm volatile("cp.async.wait_group 0;" ::: "memory");
        }
        __syncthreads();

        const int j = i + 2;
        if (j < nchunk) {
            load_chunk(ls, j);
            ls = (ls == NSTAGE - 1) ? 0 : ls + 1;
        }

        // warp-slab ldmatrix base addresses for this stage
        const uint32_t stA = smem_u32 + (cs * STAGE_F) * 4;
        const uint32_t stB = stA + TILE_F * 4;
        const uint32_t aAddr = stA + ((wm * 64 + arow) * PAD + acsh) * 4;
        const uint32_t bAddr = stB + ((wn * 32 + brow) * PAD + bcsh) * 4;
        cs = (cs == NSTAGE - 1) ? 0 : cs + 1;

#pragma unroll
        for (int kk = 0; kk < 4; kk++) {
            const int k0 = kk * 8;
            uint32_t af[4][4];
#pragma unroll
            for (int mf = 0; mf < 4; mf++)
                ldsm_x4(af[mf], aAddr + (mf * 16 * PAD + k0) * 4);
            uint32_t bf[4][2];
#pragma unroll
            for (int np = 0; np < 2; np++) {
                uint32_t bt[4];
                ldsm_x4(bt, bAddr + (np * 16 * PAD + k0) * 4);
                bf[2 * np][0]     = bt[0]; bf[2 * np][1]     = bt[1];
                bf[2 * np + 1][0] = bt[2]; bf[2 * np + 1][1] = bt[3];
            }
#pragma unroll
            for (int mf = 0; mf < 4; mf++)
#pragma unroll
                for (int nf = 0; nf < 4; nf++)
                    mma_tf32(acc[mf][nf], af[mf], bf[nf]);
        }
    }

#pragma unroll
    for (int mf = 0; mf < 4; mf++) {
        const int row = bm + wm * 64 + mf * 16 + gid;
#pragma unroll
        for (int nf = 0; nf < 4; nf++) {
            const int col = bn + wn * 32 + nf * 8 + 2 * tig;
            const float b0 = bias[col], b1 = bias[col + 1];
            float2 v0; v0.x = acc[mf][nf][0] + b0; v0.y = acc[mf][nf][1] + b1;
            float2 v1; v1.x = acc[mf][nf][2] + b0; v1.y = acc[mf][nf][3] + b1;
            *(float2*)&C[(size_t)row * N + col]       = v0;
            *(float2*)&C[(size_t)(row + 8) * N + col] = v1;
        }
    }
}

// =====================================================================
// Flash attention: tf32 mma.sync + ldmatrix, causal, GQA.
// =====================================================================
#define QT    128
#define KT    64
#define DPAD  132
#define PPAD  68
#define ATTN_SMEM_BYTES ((QT*DPAD + 2*KT*DPAD + QT*PPAD) * 4)

__global__ __launch_bounds__(256) void attn_tc_kernel(
    const float* __restrict__ QKV, float* __restrict__ Y)
{
    extern __shared__ float sm[];
    float* Qs = sm;                     // [128][132]
    float* Ks = Qs + QT * DPAD;         // [64][132]
    float* Vs = Ks + KT * DPAD;         // [64][132]
    float* Ps = Vs + KT * DPAD;         // [128][68]

    const int h   = blockIdx.y;
    const int qb  = (gridDim.x - 1) - blockIdx.x;
    const int q0  = qb * QT;
    const int kvh = h >> 2;
    const int tid = threadIdx.x;
    const int wid = tid >> 5;
    const int lane = tid & 31;
    const int gid = lane >> 2;
    const int tig = lane & 3;
    const int w16 = wid * 16;

    const int arow = lane & 15;
    const int acsh = (lane >> 4) * 4;
    const int brow = ((lane >> 4) << 3) + (lane & 7);
    const int bcsh = ((lane >> 3) & 1) * 4;

    const uint32_t smem_u32 = (uint32_t)__cvta_generic_to_shared(sm);
    const uint32_t Qs_u = smem_u32;
    const uint32_t Ks_u = Qs_u + QT * DPAD * 4;
    const uint32_t Ps_u = Ks_u + 2 * KT * DPAD * 4;   // after Ks+Vs

    const float* Qg = QKV + h * DK;
    const float* Kg = QKV + DMODEL + kvh * DK;
    const float* Vg = QKV + DMODEL + KVDIM + kvh * DK;

    for (int i = tid; i < QT * 32; i += 256) {
        const int r  = i >> 5;
        const int c4 = (i & 31) << 2;
        float4 v = *(const float4*)&Qg[(size_t)(q0 + r) * NQKV + c4];
        float4 o;
        o.x = rnaf(v.x); o.y = rnaf(v.y); o.z = rnaf(v.z); o.w = rnaf(v.w);
        *(float4*)&Qs[r * DPAD + c4] = o;
    }

    float o_acc[16][4];
#pragma unroll
    for (int nf = 0; nf < 16; nf++)
#pragma unroll
        for (int q = 0; q < 4; q++) o_acc[nf][q] = 0.0f;

    float m0 = -1e30f, m1 = -1e30f, l0 = 0.0f, l1 = 0.0f;
    const float scale = 0.08838834764831845f;
    const int rg0 = q0 + w16 + gid;
    const int rg1 = rg0 + 8;

    // ldmatrix bases (constant per CTA)
    const uint32_t qAddr = Qs_u + ((w16 + arow) * DPAD + acsh) * 4;
    const uint32_t kAddr = Ks_u + (brow * DPAD + bcsh) * 4;
    const uint32_t pAddr = Ps_u + ((w16 + arow) * PPAD + acsh) * 4;

    __syncthreads();

    const int njb = 2 * qb + 2;
    for (int jb = 0; jb < njb; jb++) {
        const int k0 = jb * KT;

        for (int i = tid; i < KT * 32; i += 256) {
            const int r  = i >> 5;
            const int c4 = (i & 31) << 2;
            const size_t goff = (size_t)(k0 + r) * NQKV + c4;
            float4 kv = *(const float4*)&Kg[goff];
            float4 vv = *(const float4*)&Vg[goff];
            float4 ko, vo;
            ko.x = rnaf(kv.x); ko.y = rnaf(kv.y); ko.z = rnaf(kv.z); ko.w = rnaf(kv.w);
            vo.x = rnaf(vv.x); vo.y = rnaf(vv.y); vo.z = rnaf(vv.z); vo.w = rnaf(vv.w);
            *(float4*)&Ks[r * DPAD + c4] = ko;
            *(float4*)&Vs[r * DPAD + c4] = vo;
        }
        __syncthreads();

        // ---- S = Q @ K^T  (ldmatrix frags) ----
        float s[8][4];
#pragma unroll
        for (int nf = 0; nf < 8; nf++)
#pragma unroll
            for (int q = 0; q < 4; q++) s[nf][q] = 0.0f;

#pragma unroll
        for (int kk = 0; kk < 16; kk++) {
            const int kd = kk * 8;
            uint32_t a[4];
            ldsm_x4(a, qAddr + kd * 4);
            uint32_t bf[8][2];
#pragma unroll
            for (int np = 0; np < 4; np++) {
                uint32_t bt[4];
                ldsm_x4(bt, kAddr + (np * 16 * DPAD + kd) * 4);
                bf[2 * np][0]     = bt[0]; bf[2 * np][1]     = bt[1];
                bf[2 * np + 1][0] = bt[2]; bf[2 * np + 1][1] = bt[3];
            }
#pragma unroll
            for (int nf = 0; nf < 8; nf++)
                mma_tf32(s[nf], a, bf[nf]);
        }

        // ---- scale + causal mask + online softmax ----
        const bool need_mask = (jb >= 2 * qb);
        float mx0 = -1e30f, mx1 = -1e30f;
#pragma unroll
        for (int nf = 0; nf < 8; nf++) {
#pragma unroll
            for (int e = 0; e < 2; e++) {
                const int jg = k0 + nf * 8 + 2 * tig + e;
                float v0 = s[nf][e]     * scale;
                float v1 = s[nf][2 + e] * scale;
                if (need_mask) {
                    if (jg > rg0) v0 = -1e30f;
                    if (jg > rg1) v1 = -1e30f;
                }
                s[nf][e]     = v0;
                s[nf][2 + e] = v1;
                mx0 = fmaxf(mx0, v0);
                mx1 = fmaxf(mx1, v1);
            }
        }
        mx0 = fmaxf(mx0, __shfl_xor_sync(0xffffffffu, mx0, 1));
        mx0 = fmaxf(mx0, __shfl_xor_sync(0xffffffffu, mx0, 2));
        mx1 = fmaxf(mx1, __shfl_xor_sync(0xffffffffu, mx1, 1));
        mx1 = fmaxf(mx1, __shfl_xor_sync(0xffffffffu, mx1, 2));

        const float mn0 = fmaxf(m0, mx0);
        const float mn1 = fmaxf(m1, mx1);
        const float al0 = __expf(m0 - mn0);
        const float al1 = __expf(m1 - mn1);
        m0 = mn0; m1 = mn1;

        float sum0 = 0.0f, sum1 = 0.0f;
#pragma unroll
        for (int nf = 0; nf < 8; nf++) {
            float p00 = __expf(s[nf][0] - mn0);
            float p01 = __expf(s[nf][1] - mn0);
            float p10 = __expf(s[nf][2] - mn1);
            float p11 = __expf(s[nf][3] - mn1);
            sum0 += p00 + p01;
            sum1 += p10 + p11;
            float2 w0; w0.x = rnaf(p00); w0.y = rnaf(p01);
            float2 w1; w1.x = rnaf(p10); w1.y = rnaf(p11);
            const int pc = nf * 8 + 2 * tig;
            *(float2*)&Ps[(w16 + gid)     * PPAD + pc] = w0;
            *(float2*)&Ps[(w16 + gid + 8) * PPAD + pc] = w1;
        }
        sum0 += __shfl_xor_sync(0xffffffffu, sum0, 1);
        sum0 += __shfl_xor_sync(0xffffffffu, sum0, 2);
        sum1 += __shfl_xor_sync(0xffffffffu, sum1, 1);
        sum1 += __shfl_xor_sync(0xffffffffu, sum1, 2);
        l0 = l0 * al0 + sum0;
        l1 = l1 * al1 + sum1;

#pragma unroll
        for (int nf = 0; nf < 16; nf++) {
            o_acc[nf][0] *= al0; o_acc[nf][1] *= al0;
            o_acc[nf][2] *= al1; o_acc[nf][3] *= al1;
        }
        __syncwarp();

        // ---- O += P @ V  (P via ldmatrix; V scalar) ----
#pragma unroll
        for (int kk = 0; kk < 8; kk++) {
            const int kb = kk * 8;
            uint32_t a[4];
            ldsm_x4(a, pAddr + kb * 4);
#pragma unroll
            for (int nf = 0; nf < 16; nf++) {
                uint32_t b[2];
                const float* vp = &Vs[(kb + tig) * DPAD + nf * 8 + gid];
                b[0] = __float_as_uint(vp[0]);
                b[1] = __float_as_uint(vp[4 * DPAD]);
                mma_tf32(o_acc[nf], a, b);
            }
        }
        __syncthreads();
    }

    const float inv0 = 1.0f / l0;
    const float inv1 = 1.0f / l1;
#pragma unroll
    for (int nf = 0; nf < 16; nf++) {
        const int col = h * DK + nf * 8 + 2 * tig;
        float2 v0, v1;
        v0.x = rnaf(o_acc[nf][0] * inv0); v0.y = rnaf(o_acc[nf][1] * inv0);
        v1.x = rnaf(o_acc[nf][2] * inv1); v1.y = rnaf(o_acc[nf][3] * inv1);
        *(float2*)&Y[(size_t)rg0 * DMODEL + col] = v0;
        *(float2*)&Y[(size_t)rg1 * DMODEL + col] = v1;
    }
}

// =====================================================================
// launch
// =====================================================================
extern "C" void kernel_launch(void* const* d_in, const int* in_sizes, int n_in,
                              void* d_out, int out_size)
{
    const float* x  = (const float*)d_in[0];
    const float* Wq = (const float*)d_in[1];
    const float* bq = (const float*)d_in[2];
    const float* Wk = (const float*)d_in[3];
    const float* bk = (const float*)d_in[4];
    const float* Wv = (const float*)d_in[5];
    const float* bv = (const float*)d_in[6];
    const float* Wo = (const float*)d_in[7];
    const float* bo = (const float*)d_in[8];
    float* out = (float*)d_out;

    float *QKVb, *Yb, *xt, *Wqkv, *bqkv, *Wot;
    cudaGetSymbolAddress((void**)&QKVb, g_QKV);
    cudaGetSymbolAddress((void**)&Yb,   g_Y);
    cudaGetSymbolAddress((void**)&xt,   g_xt);
    cudaGetSymbolAddress((void**)&Wqkv, g_Wqkv);
    cudaGetSymbolAddress((void**)&bqkv, g_bqkv);
    cudaGetSymbolAddress((void**)&Wot,  g_Wot);

    cudaFuncSetAttribute(gemm_tf32,
                         cudaFuncAttributeMaxDynamicSharedMemorySize, GEMM_SMEM_BYTES);
    cudaFuncSetAttribute(attn_tc_kernel,
                         cudaFuncAttributeMaxDynamicSharedMemorySize, ATTN_SMEM_BYTES);

    dim3 blk(256);
    const int cvt_blk = 256;
    const int n4_big = SEQ * DMODEL / 4;
    const int n4_kv  = KVDIM * DMODEL / 4;

    cvt_tf32_kernel<<<(n4_big + cvt_blk - 1) / cvt_blk, cvt_blk>>>((const float4*)x,  (float4*)xt, n4_big);
    cvt_tf32_kernel<<<(n4_big + cvt_blk - 1) / cvt_blk, cvt_blk>>>((const float4*)Wq, (float4*)(Wqkv), n4_big);
    cvt_tf32_kernel<<<(n4_kv  + cvt_blk - 1) / cvt_blk, cvt_blk>>>((const float4*)Wk, (float4*)(Wqkv + (size_t)DMODEL * DMODEL), n4_kv);
    cvt_tf32_kernel<<<(n4_kv  + cvt_blk - 1) / cvt_blk, cvt_blk>>>((const float4*)Wv, (float4*)(Wqkv + (size_t)(DMODEL + KVDIM) * DMODEL), n4_kv);
    cvt_tf32_kernel<<<(n4_big + cvt_blk - 1) / cvt_blk, cvt_blk>>>((const float4*)Wo, (float4*)Wot, n4_big);
    fuse_bias_kernel<<<(NQKV + 255) / 256, 256>>>(bq, bk, bv, bqkv);

    gemm_tf32<<<dim3(NQKV / 128, SEQ / 128), blk, GEMM_SMEM_BYTES>>>(xt, Wqkv, bqkv, QKVb, SEQ, NQKV, DMODEL);

    attn_tc_kernel<<<dim3(SEQ / QT, NHEADS), blk, ATTN_SMEM_BYTES>>>(QKVb, Yb);

    gemm_tf32<<<dim3(DMODEL / 128, SEQ / 128), blk, GEMM_SMEM_BYTES>>>(Yb, Wot, bo, out, SEQ, DMODEL, DMODEL);
}

// round 7
// speedup vs baseline: 4.9854x; 1.1377x over previous
#include <cuda_runtime.h>
#include <cstdint>
#include <math.h>

// ---------------- problem constants ----------------
#define SEQ     2048
#define DMODEL  2048
#define KVDIM   512
#define NHEADS  16
#define DK      128
#define NQKV    (DMODEL + 2 * KVDIM)    // 3072

// ---------------- scratch ----------------
__device__ float g_QKV [SEQ * NQKV];
__device__ float g_Y   [SEQ * DMODEL];
__device__ float g_xt  [SEQ * DMODEL];
__device__ float g_Wqkv[NQKV * DMODEL];
__device__ float g_bqkv[NQKV];
__device__ float g_Wot [DMODEL * DMODEL];

// =====================================================================
// helpers
// =====================================================================
__device__ __forceinline__ float rnaf(float x) {
    uint32_t u;
    asm("cvt.rna.tf32.f32 %0, %1;" : "=r"(u) : "f"(x));
    return __uint_as_float(u);
}

__device__ __forceinline__ void cpasync16(uint32_t saddr, const void* gaddr) {
    asm volatile("cp.async.cg.shared.global [%0], [%1], 16;" :: "r"(saddr), "l"(gaddr) : "memory");
}

__device__ __forceinline__ void mma_tf32(float c[4], const uint32_t a[4], const uint32_t b[2]) {
    asm volatile(
        "mma.sync.aligned.m16n8k8.row.col.f32.tf32.tf32.f32 "
        "{%0,%1,%2,%3}, {%4,%5,%6,%7}, {%8,%9}, {%0,%1,%2,%3};"
        : "+f"(c[0]), "+f"(c[1]), "+f"(c[2]), "+f"(c[3])
        : "r"(a[0]), "r"(a[1]), "r"(a[2]), "r"(a[3]), "r"(b[0]), "r"(b[1]));
}

__device__ __forceinline__ void ldsm_x4(uint32_t r[4], uint32_t addr) {
    asm volatile("ldmatrix.sync.aligned.m8n8.x4.shared.b16 {%0,%1,%2,%3}, [%4];"
                 : "=r"(r[0]), "=r"(r[1]), "=r"(r[2]), "=r"(r[3]) : "r"(addr));
}

// =====================================================================
// single fused tf32-rounding + bias-fusion pass
// =====================================================================
#define N4_BIG (SEQ * DMODEL / 4)
#define N4_KV  (KVDIM * DMODEL / 4)
#define CVT_TOTAL (3 * N4_BIG + 2 * N4_KV)

__global__ void cvt_all_kernel(
    const float4* __restrict__ x,  const float4* __restrict__ wq,
    const float4* __restrict__ wk, const float4* __restrict__ wv,
    const float4* __restrict__ wo,
    const float*  __restrict__ bq, const float* __restrict__ bk,
    const float*  __restrict__ bv,
    float4* __restrict__ xt, float4* __restrict__ wqkv,
    float4* __restrict__ wot, float* __restrict__ bqkv)
{
    int i = blockIdx.x * blockDim.x + threadIdx.x;
    if (i < CVT_TOTAL) {
        const float4* src;
        float4* dst;
        int j = i;
        if (j < N4_BIG)                    { src = x;  dst = xt; }
        else if ((j -= N4_BIG) < N4_BIG)   { src = wq; dst = wqkv; }
        else if ((j -= N4_BIG) < N4_KV)    { src = wk; dst = wqkv + N4_BIG; }
        else if ((j -= N4_KV)  < N4_KV)    { src = wv; dst = wqkv + N4_BIG + N4_KV; }
        else { j -= N4_KV;                   src = wo; dst = wot; }
        float4 v = src[j];
        float4 o;
        o.x = rnaf(v.x); o.y = rnaf(v.y); o.z = rnaf(v.z); o.w = rnaf(v.w);
        dst[j] = o;
    } else {
        int j = i - CVT_TOTAL;
        if (j < NQKV) {
            float v;
            if (j < DMODEL)              v = bq[j];
            else if (j < DMODEL + KVDIM) v = bk[j - DMODEL];
            else                         v = bv[j - DMODEL - KVDIM];
            bqkv[j] = v;
        }
    }
}

// =====================================================================
// tf32 mma.sync GEMM (ldmatrix); ROUND => epilogue rna-rounds output
// =====================================================================
#define BK      32
#define PAD     36
#define TILE_F  (128 * PAD)
#define STAGE_F (2 * TILE_F)
#define NSTAGE  3
#define GEMM_SMEM_BYTES (NSTAGE * STAGE_F * 4)

template <bool ROUND>
__global__ __launch_bounds__(256, 2) void gemm_tf32(
    const float* __restrict__ A, const float* __restrict__ B,
    const float* __restrict__ bias, float* __restrict__ C,
    int M, int N, int K)
{
    extern __shared__ float sm[];

    const int tid  = threadIdx.x;
    const int wid  = tid >> 5;
    const int lane = tid & 31;
    const int gid  = lane >> 2;
    const int tig  = lane & 3;
    const int wm   = wid >> 2;
    const int wn   = wid & 3;
    const int bm   = blockIdx.y * 128;
    const int bn   = blockIdx.x * 128;
    const int nchunk = K >> 5;

    const int arow = lane & 15;
    const int acsh = (lane >> 4) * 4;
    const int brow = ((lane >> 4) << 3) + (lane & 7);
    const int bcsh = ((lane >> 3) & 1) * 4;

    const uint32_t smem_u32 = (uint32_t)__cvta_generic_to_shared(sm);

    auto load_chunk = [&](int s, int j) {
        const uint32_t sA = smem_u32 + (s * STAGE_F) * 4;
        const uint32_t sB = sA + TILE_F * 4;
        const float* Ag = A + (size_t)bm * K + j * BK;
        const float* Bg = B + (size_t)bn * K + j * BK;
#pragma unroll
        for (int it = 0; it < 4; it++) {
            const int idx = tid + it * 256;
            const int r = idx >> 3;
            const int c = idx & 7;
            const uint32_t soff = (r * PAD + c * 4) * 4;
            cpasync16(sA + soff, Ag + (size_t)r * K + c * 4);
            cpasync16(sB + soff, Bg + (size_t)r * K + c * 4);
        }
        asm volatile("cp.async.commit_group;" ::: "memory");
    };

    float acc[4][4][4];
#pragma unroll
    for (int mf = 0; mf < 4; mf++)
#pragma unroll
        for (int nf = 0; nf < 4; nf++)
#pragma unroll
            for (int q = 0; q < 4; q++) acc[mf][nf][q] = 0.0f;

    load_chunk(0, 0);
    if (nchunk > 1) load_chunk(1, 1);

    int cs = 0;
    int ls = 2;
    for (int i = 0; i < nchunk; i++) {
        if (i + 1 < nchunk) {
            asm volatile("cp.async.wait_group 1;" ::: "memory");
        } else {
            asm volatile("cp.async.wait_group 0;" ::: "memory");
        }
        __syncthreads();

        const int j = i + 2;
        if (j < nchunk) {
            load_chunk(ls, j);
            ls = (ls == NSTAGE - 1) ? 0 : ls + 1;
        }

        const uint32_t stA = smem_u32 + (cs * STAGE_F) * 4;
        const uint32_t stB = stA + TILE_F * 4;
        const uint32_t aAddr = stA + ((wm * 64 + arow) * PAD + acsh) * 4;
        const uint32_t bAddr = stB + ((wn * 32 + brow) * PAD + bcsh) * 4;
        cs = (cs == NSTAGE - 1) ? 0 : cs + 1;

#pragma unroll
        for (int kk = 0; kk < 4; kk++) {
            const int k0 = kk * 8;
            uint32_t af[4][4];
#pragma unroll
            for (int mf = 0; mf < 4; mf++)
                ldsm_x4(af[mf], aAddr + (mf * 16 * PAD + k0) * 4);
            uint32_t bf[4][2];
#pragma unroll
            for (int np = 0; np < 2; np++) {
                uint32_t bt[4];
                ldsm_x4(bt, bAddr + (np * 16 * PAD + k0) * 4);
                bf[2 * np][0]     = bt[0]; bf[2 * np][1]     = bt[1];
                bf[2 * np + 1][0] = bt[2]; bf[2 * np + 1][1] = bt[3];
            }
#pragma unroll
            for (int mf = 0; mf < 4; mf++)
#pragma unroll
                for (int nf = 0; nf < 4; nf++)
                    mma_tf32(acc[mf][nf], af[mf], bf[nf]);
        }
    }

#pragma unroll
    for (int mf = 0; mf < 4; mf++) {
        const int row = bm + wm * 64 + mf * 16 + gid;
#pragma unroll
        for (int nf = 0; nf < 4; nf++) {
            const int col = bn + wn * 32 + nf * 8 + 2 * tig;
            const float b0 = bias[col], b1 = bias[col + 1];
            float2 v0, v1;
            if (ROUND) {
                v0.x = rnaf(acc[mf][nf][0] + b0); v0.y = rnaf(acc[mf][nf][1] + b1);
                v1.x = rnaf(acc[mf][nf][2] + b0); v1.y = rnaf(acc[mf][nf][3] + b1);
            } else {
                v0.x = acc[mf][nf][0] + b0; v0.y = acc[mf][nf][1] + b1;
                v1.x = acc[mf][nf][2] + b0; v1.y = acc[mf][nf][3] + b1;
            }
            *(float2*)&C[(size_t)row * N + col]       = v0;
            *(float2*)&C[(size_t)(row + 8) * N + col] = v1;
        }
    }
}

// =====================================================================
// Flash attention v3: Q-frags in registers, cp.async double-buffered K,
// transposed V (ldmatrix PV B-frags), 1 CTA sync per key tile.
// QKV buffer arrives PRE-ROUNDED to tf32 (GEMM epilogue).
// =====================================================================
#define QT    128
#define KT    64
#define DPAD  132
#define VPAD  68
#define PPAD  68
// smem float offsets
#define KOFF  0
#define VOFF  (2 * KT * DPAD)                 // 16896
#define POFF  (VOFF + 2 * QT * VPAD)          // 16896 + 17408 = 34304
#define ATTN_F (POFF + QT * PPAD)             // 43008
#define ATTN_SMEM_BYTES (ATTN_F * 4)          // 172032

__global__ __launch_bounds__(256, 1) void attn_tc_kernel(
    const float* __restrict__ QKV, float* __restrict__ Y)
{
    extern __shared__ float sm[];

    const int h   = blockIdx.y;
    const int qb  = (gridDim.x - 1) - blockIdx.x;
    const int q0  = qb * QT;
    const int kvh = h >> 2;
    const int tid = threadIdx.x;
    const int wid = tid >> 5;
    const int lane = tid & 31;
    const int gid = lane >> 2;
    const int tig = lane & 3;
    const int w16 = wid * 16;

    const int arow = lane & 15;
    const int acsh = (lane >> 4) * 4;
    const int brow = ((lane >> 4) << 3) + (lane & 7);
    const int bcsh = ((lane >> 3) & 1) * 4;

    const uint32_t smem_u32 = (uint32_t)__cvta_generic_to_shared(sm);

    const float* Qg = QKV + h * DK;
    const float* Kg = QKV + DMODEL + kvh * DK;
    const float* Vg = QKV + DMODEL + KVDIM + kvh * DK;

    // ---- stage Q (already tf32-rounded) into smem region 0, ldsm to regs ----
    for (int i = tid; i < QT * 32; i += 256) {
        const int r  = i >> 5;
        const int c4 = (i & 31) << 2;
        *(float4*)&sm[r * DPAD + c4] = *(const float4*)&Qg[(size_t)(q0 + r) * NQKV + c4];
    }
    __syncthreads();
    uint32_t qf[16][4];
    {
        const uint32_t qAddr = smem_u32 + ((w16 + arow) * DPAD + acsh) * 4;
#pragma unroll
        for (int kk = 0; kk < 16; kk++)
            ldsm_x4(qf[kk], qAddr + kk * 32);
    }
    __syncthreads();   // Q region about to be overwritten by K buffers

    float o_acc[16][4];
#pragma unroll
    for (int nf = 0; nf < 16; nf++)
#pragma unroll
        for (int q = 0; q < 4; q++) o_acc[nf][q] = 0.0f;

    float m0 = -1e30f, m1 = -1e30f, l0 = 0.0f, l1 = 0.0f;
    const float scale = 0.08838834764831845f;
    const int rg0 = q0 + w16 + gid;
    const int rg1 = rg0 + 8;
    const int njb = 2 * qb + 2;

    auto issue_K = [&](int jbi, int buf) {
        const float* src = Kg + (size_t)(jbi * KT) * NQKV;
        const uint32_t dst = smem_u32 + (KOFF + buf * KT * DPAD) * 4;
#pragma unroll
        for (int it = 0; it < 8; it++) {
            const int idx = tid + it * 256;
            const int r = idx >> 5;
            const int c = idx & 31;
            cpasync16(dst + (r * DPAD + c * 4) * 4, src + (size_t)r * NQKV + c * 4);
        }
        asm volatile("cp.async.commit_group;" ::: "memory");
    };

    // V loader helpers (2 4x4 blocks per thread)
    const int vbr0 = tid >> 5;              // block row 0..7   (block = 4 rows x 4 cols)
    const int vbc0 = tid & 31;              // block col 0..31
    auto ldg_V = [&](int jbi, float4 vb[2][4]) {
        const float* src = Vg + (size_t)(jbi * KT) * NQKV;
#pragma unroll
        for (int b = 0; b < 2; b++) {
            const int br = vbr0 + b * 8;     // 0..15
#pragma unroll
            for (int j = 0; j < 4; j++)
                vb[b][j] = *(const float4*)&src[(size_t)(br * 4 + j) * NQKV + vbc0 * 4];
        }
    };
    auto sts_Vt = [&](int buf, float4 vb[2][4]) {
        float* Vt = sm + VOFF + buf * QT * VPAD;
#pragma unroll
        for (int b = 0; b < 2; b++) {
            const int br = vbr0 + b * 8;
            const float* v = (const float*)vb[b];   // [j][comp] = v[j*4+comp]
#pragma unroll
            for (int k = 0; k < 4; k++) {
                float4 w;
                w.x = v[0 * 4 + k]; w.y = v[1 * 4 + k];
                w.z = v[2 * 4 + k]; w.w = v[3 * 4 + k];
                *(float4*)&Vt[(vbc0 * 4 + k) * VPAD + br * 4] = w;
            }
        }
    };

    // prologue: K0 async, V0 ldg+transpose-store into buf 0
    issue_K(0, 0);
    {
        float4 vb[2][4];
        ldg_V(0, vb);
        sts_Vt(0, vb);
    }

    const uint32_t kBase = smem_u32 + (KOFF + brow * DPAD + bcsh) * 4;
    const uint32_t vBase = smem_u32 + (VOFF + brow * VPAD + bcsh) * 4;
    const uint32_t pAddr = smem_u32 + (POFF + (w16 + arow) * PPAD + acsh) * 4;
    float* Ps = sm + POFF;

    for (int jb = 0; jb < njb; jb++) {
        const int buf = jb & 1;

        asm volatile("cp.async.wait_group 0;" ::: "memory");
        __syncthreads();   // K(jb), Vt(jb) visible; buffers buf^1 free

        const int jn = (jb + 1 < njb) ? jb + 1 : jb;
        issue_K(jn, buf ^ 1);
        float4 vb[2][4];
        ldg_V(jn, vb);

        // ---- S = Q @ K^T ----
        float s[8][4];
#pragma unroll
        for (int nf = 0; nf < 8; nf++)
#pragma unroll
            for (int q = 0; q < 4; q++) s[nf][q] = 0.0f;

        const uint32_t kAddr = kBase + (buf * KT * DPAD) * 4;
#pragma unroll
        for (int kk = 0; kk < 16; kk++) {
            const int kd = kk * 8;
            uint32_t bf[8][2];
#pragma unroll
            for (int np = 0; np < 4; np++) {
                uint32_t bt[4];
                ldsm_x4(bt, kAddr + (np * 16 * DPAD + kd) * 4);
                bf[2 * np][0]     = bt[0]; bf[2 * np][1]     = bt[1];
                bf[2 * np + 1][0] = bt[2]; bf[2 * np + 1][1] = bt[3];
            }
#pragma unroll
            for (int nf = 0; nf < 8; nf++)
                mma_tf32(s[nf], qf[kk], bf[nf]);
        }

        // ---- scale + mask + online softmax ----
        const int k0 = jb * KT;
        const bool need_mask = (jb >= 2 * qb);
        float mx0 = -1e30f, mx1 = -1e30f;
#pragma unroll
        for (int nf = 0; nf < 8; nf++) {
#pragma unroll
            for (int e = 0; e < 2; e++) {
                const int jg = k0 + nf * 8 + 2 * tig + e;
                float v0 = s[nf][e]     * scale;
                float v1 = s[nf][2 + e] * scale;
                if (need_mask) {
                    if (jg > rg0) v0 = -1e30f;
                    if (jg > rg1) v1 = -1e30f;
                }
                s[nf][e]     = v0;
                s[nf][2 + e] = v1;
                mx0 = fmaxf(mx0, v0);
                mx1 = fmaxf(mx1, v1);
            }
        }
        mx0 = fmaxf(mx0, __shfl_xor_sync(0xffffffffu, mx0, 1));
        mx0 = fmaxf(mx0, __shfl_xor_sync(0xffffffffu, mx0, 2));
        mx1 = fmaxf(mx1, __shfl_xor_sync(0xffffffffu, mx1, 1));
        mx1 = fmaxf(mx1, __shfl_xor_sync(0xffffffffu, mx1, 2));

        const float mn0 = fmaxf(m0, mx0);
        const float mn1 = fmaxf(m1, mx1);
        const float al0 = __expf(m0 - mn0);
        const float al1 = __expf(m1 - mn1);
        m0 = mn0; m1 = mn1;

        float sum0 = 0.0f, sum1 = 0.0f;
#pragma unroll
        for (int nf = 0; nf < 8; nf++) {
            float p00 = __expf(s[nf][0] - mn0);
            float p01 = __expf(s[nf][1] - mn0);
            float p10 = __expf(s[nf][2] - mn1);
            float p11 = __expf(s[nf][3] - mn1);
            sum0 += p00 + p01;
            sum1 += p10 + p11;
            float2 w0; w0.x = rnaf(p00); w0.y = rnaf(p01);
            float2 w1; w1.x = rnaf(p10); w1.y = rnaf(p11);
            const int pc = nf * 8 + 2 * tig;
            *(float2*)&Ps[(w16 + gid)     * PPAD + pc] = w0;
            *(float2*)&Ps[(w16 + gid + 8) * PPAD + pc] = w1;
        }
        sum0 += __shfl_xor_sync(0xffffffffu, sum0, 1);
        sum0 += __shfl_xor_sync(0xffffffffu, sum0, 2);
        sum1 += __shfl_xor_sync(0xffffffffu, sum1, 1);
        sum1 += __shfl_xor_sync(0xffffffffu, sum1, 2);
        l0 = l0 * al0 + sum0;
        l1 = l1 * al1 + sum1;

#pragma unroll
        for (int nf = 0; nf < 16; nf++) {
            o_acc[nf][0] *= al0; o_acc[nf][1] *= al0;
            o_acc[nf][2] *= al1; o_acc[nf][3] *= al1;
        }

        // store next V tile (transposed) into free buffer
        sts_Vt(buf ^ 1, vb);
        __syncwarp();

        // ---- O += P @ V  (P + Vt via ldmatrix) ----
        const uint32_t vAddr = vBase + (buf * QT * VPAD) * 4;
#pragma unroll
        for (int kk = 0; kk < 8; kk++) {
            const int kb = kk * 8;
            uint32_t a[4];
            ldsm_x4(a, pAddr + kb * 4);
            uint32_t bf[16][2];
#pragma unroll
            for (int np = 0; np < 8; np++) {
                uint32_t bt[4];
                ldsm_x4(bt, vAddr + (np * 16 * VPAD + kb) * 4);
                bf[2 * np][0]     = bt[0]; bf[2 * np][1]     = bt[1];
                bf[2 * np + 1][0] = bt[2]; bf[2 * np + 1][1] = bt[3];
            }
#pragma unroll
            for (int nf = 0; nf < 16; nf++)
                mma_tf32(o_acc[nf], a, bf[nf]);
        }
    }

    // ---- epilogue ----
    const float inv0 = 1.0f / l0;
    const float inv1 = 1.0f / l1;
#pragma unroll
    for (int nf = 0; nf < 16; nf++) {
        const int col = h * DK + nf * 8 + 2 * tig;
        float2 v0, v1;
        v0.x = rnaf(o_acc[nf][0] * inv0); v0.y = rnaf(o_acc[nf][1] * inv0);
        v1.x = rnaf(o_acc[nf][2] * inv1); v1.y = rnaf(o_acc[nf][3] * inv1);
        *(float2*)&Y[(size_t)rg0 * DMODEL + col] = v0;
        *(float2*)&Y[(size_t)rg1 * DMODEL + col] = v1;
    }
}

// =====================================================================
// launch
// =====================================================================
extern "C" void kernel_launch(void* const* d_in, const int* in_sizes, int n_in,
                              void* d_out, int out_size)
{
    const float* x  = (const float*)d_in[0];
    const float* Wq = (const float*)d_in[1];
    const float* bq = (const float*)d_in[2];
    const float* Wk = (const float*)d_in[3];
    const float* bk = (const float*)d_in[4];
    const float* Wv = (const float*)d_in[5];
    const float* bv = (const float*)d_in[6];
    const float* Wo = (const float*)d_in[7];
    const float* bo = (const float*)d_in[8];
    float* out = (float*)d_out;

    float *QKVb, *Yb, *xt, *Wqkv, *bqkv, *Wot;
    cudaGetSymbolAddress((void**)&QKVb, g_QKV);
    cudaGetSymbolAddress((void**)&Yb,   g_Y);
    cudaGetSymbolAddress((void**)&xt,   g_xt);
    cudaGetSymbolAddress((void**)&Wqkv, g_Wqkv);
    cudaGetSymbolAddress((void**)&bqkv, g_bqkv);
    cudaGetSymbolAddress((void**)&Wot,  g_Wot);

    cudaFuncSetAttribute(gemm_tf32<true>,
                         cudaFuncAttributeMaxDynamicSharedMemorySize, GEMM_SMEM_BYTES);
    cudaFuncSetAttribute(gemm_tf32<false>,
                         cudaFuncAttributeMaxDynamicSharedMemorySize, GEMM_SMEM_BYTES);
    cudaFuncSetAttribute(attn_tc_kernel,
                         cudaFuncAttributeMaxDynamicSharedMemorySize, ATTN_SMEM_BYTES);

    dim3 blk(256);

    const int cvt_n = CVT_TOTAL + NQKV;
    cvt_all_kernel<<<(cvt_n + 255) / 256, 256>>>(
        (const float4*)x, (const float4*)Wq, (const float4*)Wk,
        (const float4*)Wv, (const float4*)Wo,
        bq, bk, bv,
        (float4*)xt, (float4*)Wqkv, (float4*)Wot, bqkv);

    // fused QKV projection (output pre-rounded to tf32)
    gemm_tf32<true><<<dim3(NQKV / 128, SEQ / 128), blk, GEMM_SMEM_BYTES>>>(
        xt, Wqkv, bqkv, QKVb, SEQ, NQKV, DMODEL);

    attn_tc_kernel<<<dim3(SEQ / QT, NHEADS), blk, ATTN_SMEM_BYTES>>>(QKVb, Yb);

    // output projection (exact fp32 output)
    gemm_tf32<false><<<dim3(DMODEL / 128, SEQ / 128), blk, GEMM_SMEM_BYTES>>>(
        Yb, Wot, bo, out, SEQ, DMODEL, DMODEL);
}